// round 10
// baseline (speedup 1.0000x reference)
#include <cuda_runtime.h>
#include <cuda_fp16.h>
#include <cstdint>

// ---------------- scratch: hi plane at [0], lo plane at [N] ----------------
#define XT_N (32ll * 1024 * 256)
#define QK_N (32ll * 1024 * 512)
#define VT_N (32ll * 256 * 1024)
#define P_N  (32ll * 1024 * 1024)
#define AO_N (32ll * 1024 * 256)
#define WQ_N (768ll * 256)
#define WO_N (256ll * 256)

__device__ __half g_xt[2 * XT_N];
__device__ __half g_qk[2 * QK_N];
__device__ __half g_vt[2 * VT_N];
__device__ __half g_p [2 * P_N];
__device__ __half g_ao[2 * AO_N];
__device__ __half g_wq[2 * WQ_N];
__device__ __half g_wo[2 * WO_N];
__device__ float  g_scores[32ll * 1024 * 1024];

__device__ __forceinline__ uint32_t smem_u32(const void* p) {
    uint32_t a;
    asm("{ .reg .u64 t; cvta.to.shared.u64 t, %1; cvt.u32.u64 %0, t; }" : "=r"(a) : "l"(p));
    return a;
}

#define CP_ASYNC16(dst, src) \
    asm volatile("cp.async.cg.shared.global [%0], [%1], 16;" :: "r"(dst), "l"(src))
#define CP_COMMIT() asm volatile("cp.async.commit_group;")
#define CP_WAIT(n)  asm volatile("cp.async.wait_group %0;" :: "n"(n))

#define LDSM4(r0, r1, r2, r3, addr)                                               \
    asm volatile("ldmatrix.sync.aligned.m8n8.x4.shared.b16 {%0,%1,%2,%3}, [%4];"  \
                 : "=r"(r0), "=r"(r1), "=r"(r2), "=r"(r3) : "r"(addr))

#define MMA16816(c, a, b0, b1)                                                    \
    asm volatile("mma.sync.aligned.m16n8k16.row.col.f32.f16.f16.f32 "             \
                 "{%0,%1,%2,%3},{%4,%5,%6,%7},{%8,%9},{%0,%1,%2,%3};"             \
                 : "+f"((c)[0]), "+f"((c)[1]), "+f"((c)[2]), "+f"((c)[3])         \
                 : "r"((a)[0]), "r"((a)[1]), "r"((a)[2]), "r"((a)[3]),            \
                   "r"(b0), "r"(b1))

// Compact tile: 128 rows x 32 halves = 64 B/row, XOR-swizzled 16B chunks.
#define TILE_B   8192
#define OFF_AH   0
#define OFF_AL   8192
#define OFF_BH   16384
#define OFF_BL   24576
#define BUF_B    32768
#define NSTAGE   3
#define SMEM_BYTES (NSTAGE * BUF_B)        // 98304 B
#define PGRID    304                       // 2 CTAs x 152 SMs

__device__ __forceinline__ uint32_t sws(int row, int khalf) {
    return (uint32_t)(row * 64 + ((((khalf >> 3) ^ (row >> 1)) & 3) << 4));
}

__device__ __forceinline__ void split2(float v0, float v1, __half2& h, __half2& l) {
    __half h0 = __float2half_rn(v0), h1 = __float2half_rn(v1);
    h = __halves2half2(h0, h1);
    l = __halves2half2(__float2half_rn(v0 - __half2float(h0)),
                       __float2half_rn(v1 - __half2float(h1)));
}

// ======================= original (non-persistent) hgemm — used for QKV =======================
template<int K, int LDA, int LDB, int LDC,
         long long SA, long long SB, long long SC,
         long long LOFFA, long long LOFFB,
         bool HAS_BIAS, bool HAS_MASK, bool OUT_F32, bool OUT_HALF, bool QKV>
__global__ __launch_bounds__(256, 2) void hgemm(
    const __half* __restrict__ Ah, const __half* __restrict__ Bh,
    float* __restrict__ C32, __half* __restrict__ Ch, __half* __restrict__ Cl,
    __half* __restrict__ VTh, __half* __restrict__ VTl,
    float alpha, const float* __restrict__ bias_n, const int* __restrict__ maskp)
{
    extern __shared__ char smem[];
    const uint32_t sbase = smem_u32(smem);
    const int tid = threadIdx.x;
    const int wid = tid >> 5, lane = tid & 31;
    const int bz = blockIdx.z;
    const int n0 = blockIdx.x * 128, m0 = blockIdx.y * 128;
    const int warp_m = wid & 1, warp_n = wid >> 1;

    const __half* Ahb = Ah + bz * SA + (long long)m0 * LDA;
    const __half* Bhb = Bh + bz * SB + (long long)n0 * LDB;

    float acc[4][4][4];
#pragma unroll
    for (int mt = 0; mt < 4; mt++)
#pragma unroll
        for (int nt = 0; nt < 4; nt++)
#pragma unroll
            for (int r = 0; r < 4; r++) acc[mt][nt][r] = 0.f;

    auto CP_TILES = [&](int ch, int buf) {
        const int k0 = ch << 5;
        const uint32_t sb = sbase + buf * BUF_B;
#pragma unroll
        for (int i = 0; i < 2; i++) {
            const int c = tid + i * 256;
            const int row = c >> 2, part = c & 3;
            const uint32_t doff = sws(row, part << 3);
            const __half* ga = Ahb + (long long)row * LDA + k0 + part * 8;
            const __half* gb = Bhb + (long long)row * LDB + k0 + part * 8;
            CP_ASYNC16(sb + OFF_AH + doff, ga);
            CP_ASYNC16(sb + OFF_AL + doff, ga + LOFFA);
            CP_ASYNC16(sb + OFF_BH + doff, gb);
            CP_ASYNC16(sb + OFF_BL + doff, gb + LOFFB);
        }
    };

    const int a_row = warp_m * 64 + (lane & 7) + ((lane >> 3) & 1) * 8;
    const int a_kq  = (lane >> 4) * 8;
    const int b_row = warp_n * 32 + (lane >> 4) * 8 + (lane & 7);
    const int b_kq  = ((lane >> 3) & 1) * 8;

    auto COMPUTE = [&](int buf) {
        const uint32_t o = sbase + buf * BUF_B;
#pragma unroll
        for (int s = 0; s < 2; s++) {
            uint32_t bh[8], bl[8];
#pragma unroll
            for (int p = 0; p < 2; p++) {
                const int row = b_row + p * 16;
                const uint32_t boff = sws(row, s * 16 + b_kq);
                LDSM4(bh[p * 4 + 0], bh[p * 4 + 1], bh[p * 4 + 2], bh[p * 4 + 3], o + OFF_BH + boff);
                LDSM4(bl[p * 4 + 0], bl[p * 4 + 1], bl[p * 4 + 2], bl[p * 4 + 3], o + OFF_BL + boff);
            }
#pragma unroll
            for (int mt = 0; mt < 4; mt++) {
                uint32_t ah[4], al[4];
                const int row = a_row + mt * 16;
                const uint32_t aoff = sws(row, s * 16 + a_kq);
                LDSM4(ah[0], ah[1], ah[2], ah[3], o + OFF_AH + aoff);
                LDSM4(al[0], al[1], al[2], al[3], o + OFF_AL + aoff);
#pragma unroll
                for (int nt = 0; nt < 4; nt++) {
                    const int i0 = (nt >> 1) * 4 + (nt & 1) * 2;
                    MMA16816(acc[mt][nt], ah, bh[i0], bh[i0 + 1]);
                    MMA16816(acc[mt][nt], ah, bl[i0], bl[i0 + 1]);
                    MMA16816(acc[mt][nt], al, bh[i0], bh[i0 + 1]);
                }
            }
        }
    };

    constexpr int nch = K >> 5;
    CP_TILES(0, 0); CP_COMMIT();
    CP_TILES(1, 1); CP_COMMIT();
    int buf = 0, nxt = 2;
    for (int ch = 0; ch < nch; ch++) {
        if (ch + 1 < nch) { CP_WAIT(1); } else { CP_WAIT(0); }
        __syncthreads();
        if (ch + 2 < nch) {
            CP_TILES(ch + 2, nxt);
            CP_COMMIT();
        }
        COMPUTE(buf);
        buf = (buf + 1 == NSTAGE) ? 0 : buf + 1;
        nxt = (nxt + 1 == NSTAGE) ? 0 : nxt + 1;
    }

    const float NEG_INF = __int_as_float(0xff800000);
    const int gid = lane >> 2, q4 = lane & 3;
    const bool vmode = QKV && (n0 >= 512);

    if (!vmode) {
        float* C32b = OUT_F32 ? (C32 + bz * SC) : nullptr;
        __half* Chb = OUT_HALF ? (Ch + bz * SC) : nullptr;
        __half* Clb = OUT_HALF ? (Cl + bz * SC) : nullptr;
        const int* mk = HAS_MASK ? (maskp + bz * SC) : nullptr;
#pragma unroll
        for (int mt = 0; mt < 4; mt++) {
#pragma unroll
            for (int nt = 0; nt < 4; nt++) {
                const int col = n0 + warp_n * 32 + nt * 8 + q4 * 2;
                float b0 = 0.f, b1 = 0.f;
                if (HAS_BIAS) { b0 = bias_n[col]; b1 = bias_n[col + 1]; }
#pragma unroll
                for (int h = 0; h < 2; h++) {
                    const int row = m0 + warp_m * 64 + mt * 16 + gid + h * 8;
                    float v0 = acc[mt][nt][h * 2 + 0] * alpha + b0;
                    float v1 = acc[mt][nt][h * 2 + 1] * alpha + b1;
                    if (HAS_MASK) {
                        int2 mv = *reinterpret_cast<const int2*>(mk + (long long)row * 1024 + col);
                        if (mv.x != 0) v0 = NEG_INF;
                        if (mv.y != 0) v1 = NEG_INF;
                    }
                    if (OUT_F32)
                        *reinterpret_cast<float2*>(C32b + (long long)row * LDC + col) =
                            make_float2(v0, v1);
                    if (OUT_HALF) {
                        __half2 hh, ll;
                        split2(v0, v1, hh, ll);
                        *reinterpret_cast<__half2*>(Chb + (long long)row * LDC + col) = hh;
                        *reinterpret_cast<__half2*>(Clb + (long long)row * LDC + col) = ll;
                    }
                }
            }
        }
    } else {
        __syncthreads();
        __half* sh = reinterpret_cast<__half*>(smem);          // [128 d][136]
        __half* sl = sh + 128 * 136;
#pragma unroll
        for (int mt = 0; mt < 4; mt++) {
#pragma unroll
            for (int nt = 0; nt < 4; nt++) {
                const int cl0 = warp_n * 32 + nt * 8 + q4 * 2;
                const float b0 = bias_n[n0 + cl0];
                const float b1 = bias_n[n0 + cl0 + 1];
#pragma unroll
                for (int h = 0; h < 2; h++) {
                    const int rl = warp_m * 64 + mt * 16 + gid + h * 8;
                    float v0 = acc[mt][nt][h * 2 + 0] + b0;
                    float v1 = acc[mt][nt][h * 2 + 1] + b1;
                    __half h0 = __float2half_rn(v0), h1 = __float2half_rn(v1);
                    sh[cl0 * 136 + rl] = h0;
                    sh[(cl0 + 1) * 136 + rl] = h1;
                    sl[cl0 * 136 + rl] = __float2half_rn(v0 - __half2float(h0));
                    sl[(cl0 + 1) * 136 + rl] = __float2half_rn(v1 - __half2float(h1));
                }
            }
        }
        __syncthreads();
        __half* VThb = VTh + bz * (256ll * 1024);
        __half* VTlb = VTl + bz * (256ll * 1024);
#pragma unroll
        for (int i = tid; i < 128 * 16; i += 256) {
            const int d = i >> 4, seg = i & 15;
            uint4 uh = *reinterpret_cast<const uint4*>(&sh[d * 136 + seg * 8]);
            uint4 ul = *reinterpret_cast<const uint4*>(&sl[d * 136 + seg * 8]);
            const long long o2 = (long long)(n0 - 512 + d) * 1024 + m0 + seg * 8;
            *reinterpret_cast<uint4*>(&VThb[o2]) = uh;
            *reinterpret_cast<uint4*>(&VTlb[o2]) = ul;
        }
    }
}

// ======================= persistent hgemm: cross-tile cp.async pipeline =======================
// Grid = PGRID CTAs; each walks tiles bid, bid+PGRID, ... with a continuous 3-stage ring.
// Epilogues are pure-register (no SMEM) so in-flight prefetch of the next tile is safe.
template<int K, int LDA, int LDB, int LDC,
         long long SA, long long SB, long long SC,
         long long LOFFA, long long LOFFB,
         bool HAS_BIAS, bool HAS_MASK, bool OUT_F32, bool OUT_HALF,
         int NX, int NY>
__global__ __launch_bounds__(256, 2) void hgemm_p(
    const __half* __restrict__ Ah, const __half* __restrict__ Bh,
    float* __restrict__ C32, __half* __restrict__ Ch, __half* __restrict__ Cl,
    float alpha, const float* __restrict__ bias_n, const int* __restrict__ maskp)
{
    extern __shared__ char smem[];
    const uint32_t sbase = smem_u32(smem);
    const int tid = threadIdx.x;
    const int wid = tid >> 5, lane = tid & 31;
    const int bid = blockIdx.x;
    const int warp_m = wid & 1, warp_n = wid >> 1;

    constexpr int nch = K >> 5;                 // 8 or 32
    constexpr int LOG = (nch == 32) ? 5 : 3;
    constexpr int LNX = (NX == 8) ? 3 : 1;      // log2(NX), NX in {2, 8}
    constexpr int TPB = NX * NY;                // tiles per batch-slice
    constexpr int TOT = TPB * 32;
    const int num_my = (TOT - bid + PGRID - 1) / PGRID;
    const int total_chunks = num_my * nch;

    float acc[4][4][4];
#pragma unroll
    for (int mt = 0; mt < 4; mt++)
#pragma unroll
        for (int nt = 0; nt < 4; nt++)
#pragma unroll
            for (int r = 0; r < 4; r++) acc[mt][nt][r] = 0.f;

    auto PREFETCH = [&](int g, int buf) {
        const int t = g >> LOG;
        const int ch = g & (nch - 1);
        const int tile = bid + t * PGRID;
        const int bz = tile / TPB;
        const int rem = tile % TPB;
        const int tx = rem & (NX - 1), ty = rem >> LNX;
        const __half* Ahb = Ah + bz * SA + (long long)(ty * 128) * LDA + (ch << 5);
        const __half* Bhb = Bh + bz * SB + (long long)(tx * 128) * LDB + (ch << 5);
        const uint32_t sb = sbase + buf * BUF_B;
#pragma unroll
        for (int i = 0; i < 2; i++) {
            const int c = tid + i * 256;
            const int row = c >> 2, part = c & 3;
            const uint32_t doff = sws(row, part << 3);
            const __half* ga = Ahb + (long long)row * LDA + part * 8;
            const __half* gb = Bhb + (long long)row * LDB + part * 8;
            CP_ASYNC16(sb + OFF_AH + doff, ga);
            CP_ASYNC16(sb + OFF_AL + doff, ga + LOFFA);
            CP_ASYNC16(sb + OFF_BH + doff, gb);
            CP_ASYNC16(sb + OFF_BL + doff, gb + LOFFB);
        }
    };

    const int a_row = warp_m * 64 + (lane & 7) + ((lane >> 3) & 1) * 8;
    const int a_kq  = (lane >> 4) * 8;
    const int b_row = warp_n * 32 + (lane >> 4) * 8 + (lane & 7);
    const int b_kq  = ((lane >> 3) & 1) * 8;

    auto COMPUTE = [&](int buf) {
        const uint32_t o = sbase + buf * BUF_B;
#pragma unroll
        for (int s = 0; s < 2; s++) {
            uint32_t bh[8], bl[8];
#pragma unroll
            for (int p = 0; p < 2; p++) {
                const int row = b_row + p * 16;
                const uint32_t boff = sws(row, s * 16 + b_kq);
                LDSM4(bh[p * 4 + 0], bh[p * 4 + 1], bh[p * 4 + 2], bh[p * 4 + 3], o + OFF_BH + boff);
                LDSM4(bl[p * 4 + 0], bl[p * 4 + 1], bl[p * 4 + 2], bl[p * 4 + 3], o + OFF_BL + boff);
            }
#pragma unroll
            for (int mt = 0; mt < 4; mt++) {
                uint32_t ah[4], al[4];
                const int row = a_row + mt * 16;
                const uint32_t aoff = sws(row, s * 16 + a_kq);
                LDSM4(ah[0], ah[1], ah[2], ah[3], o + OFF_AH + aoff);
                LDSM4(al[0], al[1], al[2], al[3], o + OFF_AL + aoff);
#pragma unroll
                for (int nt = 0; nt < 4; nt++) {
                    const int i0 = (nt >> 1) * 4 + (nt & 1) * 2;
                    MMA16816(acc[mt][nt], ah, bh[i0], bh[i0 + 1]);
                    MMA16816(acc[mt][nt], ah, bl[i0], bl[i0 + 1]);
                    MMA16816(acc[mt][nt], al, bh[i0], bh[i0 + 1]);
                }
            }
        }
    };

    const float NEG_INF = __int_as_float(0xff800000);
    const int gid = lane >> 2, q4 = lane & 3;

    auto EPILOGUE = [&](int tile) {
        const int bz = tile / TPB;
        const int rem = tile % TPB;
        const int n0 = (rem & (NX - 1)) * 128;
        const int m0 = (rem >> LNX) * 128;
        float* C32b = OUT_F32 ? (C32 + bz * SC) : nullptr;
        __half* Chb = OUT_HALF ? (Ch + bz * SC) : nullptr;
        __half* Clb = OUT_HALF ? (Cl + bz * SC) : nullptr;
        const int* mk = HAS_MASK ? (maskp + bz * SC) : nullptr;
#pragma unroll
        for (int mt = 0; mt < 4; mt++) {
#pragma unroll
            for (int nt = 0; nt < 4; nt++) {
                const int col = n0 + warp_n * 32 + nt * 8 + q4 * 2;
                float b0 = 0.f, b1 = 0.f;
                if (HAS_BIAS) { b0 = bias_n[col]; b1 = bias_n[col + 1]; }
#pragma unroll
                for (int h = 0; h < 2; h++) {
                    const int row = m0 + warp_m * 64 + mt * 16 + gid + h * 8;
                    float v0 = acc[mt][nt][h * 2 + 0] * alpha + b0;
                    float v1 = acc[mt][nt][h * 2 + 1] * alpha + b1;
                    if (HAS_MASK) {
                        int2 mv = *reinterpret_cast<const int2*>(mk + (long long)row * 1024 + col);
                        if (mv.x != 0) v0 = NEG_INF;
                        if (mv.y != 0) v1 = NEG_INF;
                    }
                    if (OUT_F32)
                        *reinterpret_cast<float2*>(C32b + (long long)row * LDC + col) =
                            make_float2(v0, v1);
                    if (OUT_HALF) {
                        __half2 hh, ll;
                        split2(v0, v1, hh, ll);
                        *reinterpret_cast<__half2*>(Chb + (long long)row * LDC + col) = hh;
                        *reinterpret_cast<__half2*>(Clb + (long long)row * LDC + col) = ll;
                    }
                    acc[mt][nt][h * 2 + 0] = 0.f;
                    acc[mt][nt][h * 2 + 1] = 0.f;
                }
            }
        }
    };

    // continuous pipeline across all of this CTA's tiles
    PREFETCH(0, 0); CP_COMMIT();
    PREFETCH(1, 1); CP_COMMIT();
    int buf = 0, nxt = 2;
    for (int g = 0; g < total_chunks; g++) {
        if (g + 1 < total_chunks) { CP_WAIT(1); } else { CP_WAIT(0); }
        __syncthreads();
        if (g + 2 < total_chunks) {
            PREFETCH(g + 2, nxt);
            CP_COMMIT();
        }
        COMPUTE(buf);
        buf = (buf + 1 == NSTAGE) ? 0 : buf + 1;
        nxt = (nxt + 1 == NSTAGE) ? 0 : nxt + 1;
        if (((g + 1) & (nch - 1)) == 0)
            EPILOGUE(bid + (g >> LOG) * PGRID);
    }
}

// ---------------- transpose x: (bc, 256, 1024) -> (bc, 1024, 256) hi/lo ----------
__global__ __launch_bounds__(256) void transpose_kernel(
    const float* __restrict__ x, __half* __restrict__ xh, __half* __restrict__ xl)
{
    __shared__ float tile[32][33];
    const int bz = blockIdx.z;
    const float* xs = x + (long long)bz * 256 * 1024;
    __half* xhd = xh + (long long)bz * 1024 * 256;
    __half* xld = xl + (long long)bz * 1024 * 256;
    const int t0 = blockIdx.x * 32, d0 = blockIdx.y * 32;
    const int tx = threadIdx.x, ty = threadIdx.y;
#pragma unroll
    for (int k = 0; k < 4; k++)
        tile[ty + k * 8][tx] = xs[(long long)(d0 + ty + k * 8) * 1024 + t0 + tx];
    __syncthreads();
#pragma unroll
    for (int k = 0; k < 4; k++) {
        float v = tile[tx][ty + k * 8];
        __half h = __float2half_rn(v);
        long long o = (long long)(t0 + ty + k * 8) * 256 + d0 + tx;
        xhd[o] = h;
        xld[o] = __float2half_rn(v - __half2float(h));
    }
}

// ---------------- weight fp32 -> hi/lo halves ----------------
__global__ void cvt_kernel(const float* __restrict__ w,
                           __half* __restrict__ h, __half* __restrict__ l, int n)
{
    int i = blockIdx.x * 256 + threadIdx.x;
    if (i < n) {
        float v = w[i];
        __half hh = __float2half_rn(v);
        h[i] = hh;
        l[i] = __float2half_rn(v - __half2float(hh));
    }
}

// ---------------- row softmax (fp32 in) -> P hi/lo halves ----------------
__global__ __launch_bounds__(256) void softmax_kernel(
    const float* __restrict__ S, __half* __restrict__ Ph, __half* __restrict__ Pl)
{
    const long long row = blockIdx.x;
    const float* p = S + row * 1024;
    const int tid = threadIdx.x;

    float4 v = reinterpret_cast<const float4*>(p)[tid];
    float m = fmaxf(fmaxf(v.x, v.y), fmaxf(v.z, v.w));
#pragma unroll
    for (int o = 16; o; o >>= 1) m = fmaxf(m, __shfl_xor_sync(0xffffffffu, m, o));

    __shared__ float red[8];
    if ((tid & 31) == 0) red[tid >> 5] = m;
    __syncthreads();
    float mm = red[0];
#pragma unroll
    for (int w = 1; w < 8; w++) mm = fmaxf(mm, red[w]);
    __syncthreads();

    float e0 = (v.x <= -1e30f) ? 0.f : __expf(v.x - mm);
    float e1 = (v.y <= -1e30f) ? 0.f : __expf(v.y - mm);
    float e2 = (v.z <= -1e30f) ? 0.f : __expf(v.z - mm);
    float e3 = (v.w <= -1e30f) ? 0.f : __expf(v.w - mm);

    float s = e0 + e1 + e2 + e3;
#pragma unroll
    for (int o = 16; o; o >>= 1) s += __shfl_xor_sync(0xffffffffu, s, o);
    if ((tid & 31) == 0) red[tid >> 5] = s;
    __syncthreads();
    float tot = red[0];
#pragma unroll
    for (int w = 1; w < 8; w++) tot += red[w];

    float inv = 1.0f / tot;
    float o0 = e0 * inv, o1 = e1 * inv, o2 = e2 * inv, o3 = e3 * inv;
    __half2 h01, l01, h23, l23;
    split2(o0, o1, h01, l01);
    split2(o2, o3, h23, l23);
    *reinterpret_cast<uint2*>(Ph + row * 1024 + tid * 4) =
        make_uint2(*reinterpret_cast<uint32_t*>(&h01), *reinterpret_cast<uint32_t*>(&h23));
    *reinterpret_cast<uint2*>(Pl + row * 1024 + tid * 4) =
        make_uint2(*reinterpret_cast<uint32_t*>(&l01), *reinterpret_cast<uint32_t*>(&l23));
}

extern "C" void kernel_launch(void* const* d_in, const int* in_sizes, int n_in,
                              void* d_out, int out_size)
{
    const float* x     = (const float*)d_in[0];   // (8,4,256,1024)
    const int*   mask  = (const int*)d_in[1];     // (8,4,1024,1024) bool -> int32
    const float* w_qkv = (const float*)d_in[2];   // (768,256)
    const float* b_qkv = (const float*)d_in[3];   // (768,)
    const float* w_out = (const float*)d_in[4];   // (256,256)
    const float* b_out = (const float*)d_in[5];   // (256,)
    float*       out   = (float*)d_out;           // (8,4,1024,256)

    __half *xt, *qk, *vt, *pp, *ao, *wq, *wo;
    float* scores;
    cudaGetSymbolAddress((void**)&xt, g_xt);
    cudaGetSymbolAddress((void**)&qk, g_qk);
    cudaGetSymbolAddress((void**)&vt, g_vt);
    cudaGetSymbolAddress((void**)&pp, g_p);
    cudaGetSymbolAddress((void**)&ao, g_ao);
    cudaGetSymbolAddress((void**)&wq, g_wq);
    cudaGetSymbolAddress((void**)&wo, g_wo);
    cudaGetSymbolAddress((void**)&scores, g_scores);

    // 0) converters
    transpose_kernel<<<dim3(32, 8, 32), dim3(32, 8)>>>(x, xt, xt + XT_N);
    cvt_kernel<<<768, 256>>>(w_qkv, wq, wq + WQ_N, 768 * 256);
    cvt_kernel<<<256, 256>>>(w_out, wo, wo + WO_N, 256 * 256);

    // 1) QKV (non-persistent; V-mode epilogue uses SMEM staging)
    {
        auto kfn = hgemm<256, 256, 256, 512, 1024ll * 256, 0ll, 1024ll * 512,
                         XT_N, WQ_N, true, false, false, true, true>;
        cudaFuncSetAttribute(kfn, cudaFuncAttributeMaxDynamicSharedMemorySize, SMEM_BYTES);
        kfn<<<dim3(6, 8, 32), 256, SMEM_BYTES>>>(
            xt, wq, nullptr, qk, qk + QK_N, vt, vt + VT_N, 1.0f, b_qkv, nullptr);
    }

    // 2) scores (fp32) = scale * Q @ K^T, mask -> -inf   [persistent, 8x8 tiles]
    {
        auto kfn = hgemm_p<256, 512, 512, 1024, 1024ll * 512, 1024ll * 512, 1024ll * 1024,
                           QK_N, QK_N, false, true, true, false, 8, 8>;
        cudaFuncSetAttribute(kfn, cudaFuncAttributeMaxDynamicSharedMemorySize, SMEM_BYTES);
        kfn<<<PGRID, 256, SMEM_BYTES>>>(
            qk, qk + 256, scores, nullptr, nullptr, 0.0625f, nullptr, mask);
    }

    // 3) softmax -> P halves
    softmax_kernel<<<32 * 1024, 256>>>(scores, pp, pp + P_N);

    // 4) attnO halves = P @ V   [persistent, 2x8 tiles]
    {
        auto kfn = hgemm_p<1024, 1024, 1024, 256, 1024ll * 1024, 256ll * 1024, 1024ll * 256,
                           P_N, VT_N, false, false, false, true, 2, 8>;
        cudaFuncSetAttribute(kfn, cudaFuncAttributeMaxDynamicSharedMemorySize, SMEM_BYTES);
        kfn<<<PGRID, 256, SMEM_BYTES>>>(
            pp, vt, nullptr, ao, ao + AO_N, 1.0f, nullptr, nullptr);
    }

    // 5) out (fp32) = attnO @ w_out^T + b_out   [persistent, 2x8 tiles]
    {
        auto kfn = hgemm_p<256, 256, 256, 256, 1024ll * 256, 0ll, 1024ll * 256,
                           AO_N, WO_N, true, false, true, false, 2, 8>;
        cudaFuncSetAttribute(kfn, cudaFuncAttributeMaxDynamicSharedMemorySize, SMEM_BYTES);
        kfn<<<PGRID, 256, SMEM_BYTES>>>(
            ao, wo, out, nullptr, nullptr, 1.0f, b_out, nullptr);
    }
}

// round 11
// speedup vs baseline: 1.2786x; 1.2786x over previous
#include <cuda_runtime.h>
#include <cuda_fp16.h>
#include <cstdint>

// ---------------- scratch: hi plane at [0], lo plane at [N] ----------------
#define XT_N (32ll * 1024 * 256)
#define QK_N (32ll * 1024 * 512)
#define VT_N (32ll * 256 * 1024)
#define P_N  (32ll * 1024 * 1024)
#define AO_N (32ll * 1024 * 256)
#define WQ_N (768ll * 256)
#define WO_N (256ll * 256)

__device__ __half g_xt[2 * XT_N];
__device__ __half g_qk[2 * QK_N];
__device__ __half g_vt[2 * VT_N];
__device__ __half g_p [2 * P_N];
__device__ __half g_ao[2 * AO_N];
__device__ __half g_wq[2 * WQ_N];
__device__ __half g_wo[2 * WO_N];
__device__ float  g_scores[32ll * 1024 * 1024];

__device__ __forceinline__ uint32_t smem_u32(const void* p) {
    uint32_t a;
    asm("{ .reg .u64 t; cvta.to.shared.u64 t, %1; cvt.u32.u64 %0, t; }" : "=r"(a) : "l"(p));
    return a;
}

#define CP_ASYNC16(dst, src) \
    asm volatile("cp.async.cg.shared.global [%0], [%1], 16;" :: "r"(dst), "l"(src))
#define CP_COMMIT() asm volatile("cp.async.commit_group;")
#define CP_WAIT(n)  asm volatile("cp.async.wait_group %0;" :: "n"(n))

#define LDSM4(r0, r1, r2, r3, addr)                                               \
    asm volatile("ldmatrix.sync.aligned.m8n8.x4.shared.b16 {%0,%1,%2,%3}, [%4];"  \
                 : "=r"(r0), "=r"(r1), "=r"(r2), "=r"(r3) : "r"(addr))

#define MMA16816(c, a, b0, b1)                                                    \
    asm volatile("mma.sync.aligned.m16n8k16.row.col.f32.f16.f16.f32 "             \
                 "{%0,%1,%2,%3},{%4,%5,%6,%7},{%8,%9},{%0,%1,%2,%3};"             \
                 : "+f"((c)[0]), "+f"((c)[1]), "+f"((c)[2]), "+f"((c)[3])         \
                 : "r"((a)[0]), "r"((a)[1]), "r"((a)[2]), "r"((a)[3]),            \
                   "r"(b0), "r"(b1))

// Compact tile: 128 rows x 32 halves = 64 B/row, XOR-swizzled 16B chunks.
// 2-pass split: A needs hi+lo tiles, B needs hi only -> 3 tiles/stage.
#define TILE_B   8192
#define OFF_AH   0
#define OFF_AL   8192
#define OFF_BH   16384
#define BUF_B    24576
#define NSTAGE   3
#define SMEM_BYTES (NSTAGE * BUF_B)        // 73728 B

__device__ __forceinline__ uint32_t sws(int row, int khalf) {
    return (uint32_t)(row * 64 + ((((khalf >> 3) ^ (row >> 1)) & 3) << 4));
}

__device__ __forceinline__ void split2(float v0, float v1, __half2& h, __half2& l) {
    __half h0 = __float2half_rn(v0), h1 = __float2half_rn(v1);
    h = __halves2half2(h0, h1);
    l = __halves2half2(__float2half_rn(v0 - __half2float(h0)),
                       __float2half_rn(v1 - __half2float(h1)));
}

// C[128 x 128 tile] = A(m,k) . B(n,k)^T; A = hi+lo fp16 split (exact), B = fp16-rounded.
// 2-pass: ah.bh + al.bh  ->  ~1e-4 relative accuracy.
template<int K, int LDA, int LDB, int LDC,
         long long SA, long long SB, long long SC,
         long long LOFFA,
         bool HAS_BIAS, bool HAS_MASK, bool OUT_F32, bool OUT_HALF, bool QKV>
__global__ __launch_bounds__(256, 2) void hgemm(
    const __half* __restrict__ Ah, const __half* __restrict__ Bh,
    float* __restrict__ C32, __half* __restrict__ Ch, __half* __restrict__ Cl,
    __half* __restrict__ VTh, __half* __restrict__ VTl,
    float alpha, const float* __restrict__ bias_n, const int* __restrict__ maskp)
{
    extern __shared__ char smem[];
    const uint32_t sbase = smem_u32(smem);
    const int tid = threadIdx.x;
    const int wid = tid >> 5, lane = tid & 31;
    const int bz = blockIdx.z;
    const int n0 = blockIdx.x * 128, m0 = blockIdx.y * 128;
    const int warp_m = wid & 1, warp_n = wid >> 1;   // 2 x 4 warp grid

    const __half* Ahb = Ah + bz * SA + (long long)m0 * LDA;
    const __half* Bhb = Bh + bz * SB + (long long)n0 * LDB;

    float acc[4][4][4];
#pragma unroll
    for (int mt = 0; mt < 4; mt++)
#pragma unroll
        for (int nt = 0; nt < 4; nt++)
#pragma unroll
            for (int r = 0; r < 4; r++) acc[mt][nt][r] = 0.f;

    // 3 tiles x 512 16B-chunks / 256 threads
    auto CP_TILES = [&](int ch, int buf) {
        const int k0 = ch << 5;
        const uint32_t sb = sbase + buf * BUF_B;
#pragma unroll
        for (int i = 0; i < 2; i++) {
            const int c = tid + i * 256;            // 0..511
            const int row = c >> 2, part = c & 3;
            const uint32_t doff = sws(row, part << 3);
            const __half* ga = Ahb + (long long)row * LDA + k0 + part * 8;
            const __half* gb = Bhb + (long long)row * LDB + k0 + part * 8;
            CP_ASYNC16(sb + OFF_AH + doff, ga);
            CP_ASYNC16(sb + OFF_AL + doff, ga + LOFFA);
            CP_ASYNC16(sb + OFF_BH + doff, gb);
        }
    };

    // lane-derived ldmatrix row/col bases
    const int a_row = warp_m * 64 + (lane & 7) + ((lane >> 3) & 1) * 8;
    const int a_kq  = (lane >> 4) * 8;
    const int b_row = warp_n * 32 + (lane >> 4) * 8 + (lane & 7);
    const int b_kq  = ((lane >> 3) & 1) * 8;

    auto COMPUTE = [&](int buf) {
        const uint32_t o = sbase + buf * BUF_B;
#pragma unroll
        for (int s = 0; s < 2; s++) {
            uint32_t bh[8];
#pragma unroll
            for (int p = 0; p < 2; p++) {
                const int row = b_row + p * 16;
                const uint32_t boff = sws(row, s * 16 + b_kq);
                LDSM4(bh[p * 4 + 0], bh[p * 4 + 1], bh[p * 4 + 2], bh[p * 4 + 3], o + OFF_BH + boff);
            }
#pragma unroll
            for (int mt = 0; mt < 4; mt++) {
                uint32_t ah[4], al[4];
                const int row = a_row + mt * 16;
                const uint32_t aoff = sws(row, s * 16 + a_kq);
                LDSM4(ah[0], ah[1], ah[2], ah[3], o + OFF_AH + aoff);
                LDSM4(al[0], al[1], al[2], al[3], o + OFF_AL + aoff);
#pragma unroll
                for (int nt = 0; nt < 4; nt++) {
                    const int i0 = (nt >> 1) * 4 + (nt & 1) * 2;
                    MMA16816(acc[mt][nt], ah, bh[i0], bh[i0 + 1]);
                }
#pragma unroll
                for (int nt = 0; nt < 4; nt++) {
                    const int i0 = (nt >> 1) * 4 + (nt & 1) * 2;
                    MMA16816(acc[mt][nt], al, bh[i0], bh[i0 + 1]);
                }
            }
        }
    };

    // 3-stage pipeline, one barrier per chunk
    constexpr int nch = K >> 5;
    CP_TILES(0, 0); CP_COMMIT();
    CP_TILES(1, 1); CP_COMMIT();
    int buf = 0, nxt = 2;
    for (int ch = 0; ch < nch; ch++) {
        if (ch + 1 < nch) { CP_WAIT(1); } else { CP_WAIT(0); }
        __syncthreads();
        if (ch + 2 < nch) {
            CP_TILES(ch + 2, nxt);
            CP_COMMIT();
        }
        COMPUTE(buf);
        buf = (buf + 1 == NSTAGE) ? 0 : buf + 1;
        nxt = (nxt + 1 == NSTAGE) ? 0 : nxt + 1;
    }

    // ---------------- epilogue ----------------
    const float NEG_INF = __int_as_float(0xff800000);
    const int gid = lane >> 2, q4 = lane & 3;
    const bool vmode = QKV && (n0 >= 512);

    if (!vmode) {
        float* C32b = OUT_F32 ? (C32 + bz * SC) : nullptr;
        __half* Chb = OUT_HALF ? (Ch + bz * SC) : nullptr;
        __half* Clb = OUT_HALF ? (Cl + bz * SC) : nullptr;
        const int* mk = HAS_MASK ? (maskp + bz * SC) : nullptr;
#pragma unroll
        for (int mt = 0; mt < 4; mt++) {
#pragma unroll
            for (int nt = 0; nt < 4; nt++) {
                const int col = n0 + warp_n * 32 + nt * 8 + q4 * 2;
                float b0 = 0.f, b1 = 0.f;
                if (HAS_BIAS) { b0 = bias_n[col]; b1 = bias_n[col + 1]; }
#pragma unroll
                for (int h = 0; h < 2; h++) {
                    const int row = m0 + warp_m * 64 + mt * 16 + gid + h * 8;
                    float v0 = acc[mt][nt][h * 2 + 0] * alpha + b0;
                    float v1 = acc[mt][nt][h * 2 + 1] * alpha + b1;
                    if (HAS_MASK) {
                        int2 mv = *reinterpret_cast<const int2*>(mk + (long long)row * 1024 + col);
                        if (mv.x != 0) v0 = NEG_INF;
                        if (mv.y != 0) v1 = NEG_INF;
                    }
                    if (OUT_F32)
                        *reinterpret_cast<float2*>(C32b + (long long)row * LDC + col) =
                            make_float2(v0, v1);
                    if (OUT_HALF) {
                        __half2 hh, ll;
                        split2(v0, v1, hh, ll);
                        *reinterpret_cast<__half2*>(Chb + (long long)row * LDC + col) = hh;
                        *reinterpret_cast<__half2*>(Clb + (long long)row * LDC + col) = ll;
                    }
                }
            }
        }
    } else {
        // V part of QKV: stage transposed in SMEM, then coalesced 16B stores.
        __syncthreads();
        __half* sh = reinterpret_cast<__half*>(smem);          // [128 d][136]
        __half* sl = sh + 128 * 136;
#pragma unroll
        for (int mt = 0; mt < 4; mt++) {
#pragma unroll
            for (int nt = 0; nt < 4; nt++) {
                const int cl0 = warp_n * 32 + nt * 8 + q4 * 2;
                const float b0 = bias_n[n0 + cl0];
                const float b1 = bias_n[n0 + cl0 + 1];
#pragma unroll
                for (int h = 0; h < 2; h++) {
                    const int rl = warp_m * 64 + mt * 16 + gid + h * 8;
                    float v0 = acc[mt][nt][h * 2 + 0] + b0;
                    float v1 = acc[mt][nt][h * 2 + 1] + b1;
                    __half h0 = __float2half_rn(v0), h1 = __float2half_rn(v1);
                    sh[cl0 * 136 + rl] = h0;
                    sh[(cl0 + 1) * 136 + rl] = h1;
                    sl[cl0 * 136 + rl] = __float2half_rn(v0 - __half2float(h0));
                    sl[(cl0 + 1) * 136 + rl] = __float2half_rn(v1 - __half2float(h1));
                }
            }
        }
        __syncthreads();
        __half* VThb = VTh + bz * (256ll * 1024);
        __half* VTlb = VTl + bz * (256ll * 1024);
#pragma unroll
        for (int i = tid; i < 128 * 16; i += 256) {
            const int d = i >> 4, seg = i & 15;
            uint4 uh = *reinterpret_cast<const uint4*>(&sh[d * 136 + seg * 8]);
            uint4 ul = *reinterpret_cast<const uint4*>(&sl[d * 136 + seg * 8]);
            const long long o2 = (long long)(n0 - 512 + d) * 1024 + m0 + seg * 8;
            *reinterpret_cast<uint4*>(&VThb[o2]) = uh;
            *reinterpret_cast<uint4*>(&VTlb[o2]) = ul;
        }
    }
}

// ---------------- transpose x: (bc, 256, 1024) -> (bc, 1024, 256) hi/lo ----------
__global__ __launch_bounds__(256) void transpose_kernel(
    const float* __restrict__ x, __half* __restrict__ xh, __half* __restrict__ xl)
{
    __shared__ float tile[32][33];
    const int bz = blockIdx.z;
    const float* xs = x + (long long)bz * 256 * 1024;
    __half* xhd = xh + (long long)bz * 1024 * 256;
    __half* xld = xl + (long long)bz * 1024 * 256;
    const int t0 = blockIdx.x * 32, d0 = blockIdx.y * 32;
    const int tx = threadIdx.x, ty = threadIdx.y;
#pragma unroll
    for (int k = 0; k < 4; k++)
        tile[ty + k * 8][tx] = xs[(long long)(d0 + ty + k * 8) * 1024 + t0 + tx];
    __syncthreads();
#pragma unroll
    for (int k = 0; k < 4; k++) {
        float v = tile[tx][ty + k * 8];
        __half h = __float2half_rn(v);
        long long o = (long long)(t0 + ty + k * 8) * 256 + d0 + tx;
        xhd[o] = h;
        xld[o] = __float2half_rn(v - __half2float(h));
    }
}

// ---------------- weight fp32 -> hi/lo halves ----------------
__global__ void cvt_kernel(const float* __restrict__ w,
                           __half* __restrict__ h, __half* __restrict__ l, int n)
{
    int i = blockIdx.x * 256 + threadIdx.x;
    if (i < n) {
        float v = w[i];
        __half hh = __float2half_rn(v);
        h[i] = hh;
        l[i] = __float2half_rn(v - __half2float(hh));
    }
}

// ---------------- row softmax (fp32 in) -> P hi/lo halves ----------------
__global__ __launch_bounds__(256) void softmax_kernel(
    const float* __restrict__ S, __half* __restrict__ Ph, __half* __restrict__ Pl)
{
    const long long row = blockIdx.x;
    const float* p = S + row * 1024;
    const int tid = threadIdx.x;

    float4 v = reinterpret_cast<const float4*>(p)[tid];
    float m = fmaxf(fmaxf(v.x, v.y), fmaxf(v.z, v.w));
#pragma unroll
    for (int o = 16; o; o >>= 1) m = fmaxf(m, __shfl_xor_sync(0xffffffffu, m, o));

    __shared__ float red[8];
    if ((tid & 31) == 0) red[tid >> 5] = m;
    __syncthreads();
    float mm = red[0];
#pragma unroll
    for (int w = 1; w < 8; w++) mm = fmaxf(mm, red[w]);
    __syncthreads();

    float e0 = (v.x <= -1e30f) ? 0.f : __expf(v.x - mm);
    float e1 = (v.y <= -1e30f) ? 0.f : __expf(v.y - mm);
    float e2 = (v.z <= -1e30f) ? 0.f : __expf(v.z - mm);
    float e3 = (v.w <= -1e30f) ? 0.f : __expf(v.w - mm);

    float s = e0 + e1 + e2 + e3;
#pragma unroll
    for (int o = 16; o; o >>= 1) s += __shfl_xor_sync(0xffffffffu, s, o);
    if ((tid & 31) == 0) red[tid >> 5] = s;
    __syncthreads();
    float tot = red[0];
#pragma unroll
    for (int w = 1; w < 8; w++) tot += red[w];

    float inv = 1.0f / tot;
    float o0 = e0 * inv, o1 = e1 * inv, o2 = e2 * inv, o3 = e3 * inv;
    __half2 h01, l01, h23, l23;
    split2(o0, o1, h01, l01);
    split2(o2, o3, h23, l23);
    *reinterpret_cast<uint2*>(Ph + row * 1024 + tid * 4) =
        make_uint2(*reinterpret_cast<uint32_t*>(&h01), *reinterpret_cast<uint32_t*>(&h23));
    *reinterpret_cast<uint2*>(Pl + row * 1024 + tid * 4) =
        make_uint2(*reinterpret_cast<uint32_t*>(&l01), *reinterpret_cast<uint32_t*>(&l23));
}

extern "C" void kernel_launch(void* const* d_in, const int* in_sizes, int n_in,
                              void* d_out, int out_size)
{
    const float* x     = (const float*)d_in[0];   // (8,4,256,1024)
    const int*   mask  = (const int*)d_in[1];     // (8,4,1024,1024) bool -> int32
    const float* w_qkv = (const float*)d_in[2];   // (768,256)
    const float* b_qkv = (const float*)d_in[3];   // (768,)
    const float* w_out = (const float*)d_in[4];   // (256,256)
    const float* b_out = (const float*)d_in[5];   // (256,)
    float*       out   = (float*)d_out;           // (8,4,1024,256)

    __half *xt, *qk, *vt, *pp, *ao, *wq, *wo;
    float* scores;
    cudaGetSymbolAddress((void**)&xt, g_xt);
    cudaGetSymbolAddress((void**)&qk, g_qk);
    cudaGetSymbolAddress((void**)&vt, g_vt);
    cudaGetSymbolAddress((void**)&pp, g_p);
    cudaGetSymbolAddress((void**)&ao, g_ao);
    cudaGetSymbolAddress((void**)&wq, g_wq);
    cudaGetSymbolAddress((void**)&wo, g_wo);
    cudaGetSymbolAddress((void**)&scores, g_scores);

    // 0) converters
    transpose_kernel<<<dim3(32, 8, 32), dim3(32, 8)>>>(x, xt, xt + XT_N);
    cvt_kernel<<<768, 256>>>(w_qkv, wq, wq + WQ_N, 768 * 256);
    cvt_kernel<<<256, 256>>>(w_out, wo, wo + WO_N, 256 * 256);

    // 1) QKV: A = xt (split), B = w_qkv (fp16)
    {
        auto kfn = hgemm<256, 256, 256, 512, 1024ll * 256, 0ll, 1024ll * 512,
                         XT_N, true, false, false, true, true>;
        cudaFuncSetAttribute(kfn, cudaFuncAttributeMaxDynamicSharedMemorySize, SMEM_BYTES);
        kfn<<<dim3(6, 8, 32), 256, SMEM_BYTES>>>(
            xt, wq, nullptr, qk, qk + QK_N, vt, vt + VT_N, 1.0f, b_qkv, nullptr);
    }

    // 2) scores (fp32) = scale * Q (split) @ K (fp16)^T, mask -> -inf
    {
        auto kfn = hgemm<256, 512, 512, 1024, 1024ll * 512, 1024ll * 512, 1024ll * 1024,
                         QK_N, false, true, true, false, false>;
        cudaFuncSetAttribute(kfn, cudaFuncAttributeMaxDynamicSharedMemorySize, SMEM_BYTES);
        kfn<<<dim3(8, 8, 32), 256, SMEM_BYTES>>>(
            qk, qk + 256, scores, nullptr, nullptr, nullptr, nullptr,
            0.0625f, nullptr, mask);
    }

    // 3) softmax -> P halves
    softmax_kernel<<<32 * 1024, 256>>>(scores, pp, pp + P_N);

    // 4) attnO halves = P (split) @ V (fp16)
    {
        auto kfn = hgemm<1024, 1024, 1024, 256, 1024ll * 1024, 256ll * 1024, 1024ll * 256,
                         P_N, false, false, false, true, false>;
        cudaFuncSetAttribute(kfn, cudaFuncAttributeMaxDynamicSharedMemorySize, SMEM_BYTES);
        kfn<<<dim3(2, 8, 32), 256, SMEM_BYTES>>>(
            pp, vt, nullptr, ao, ao + AO_N, nullptr, nullptr, 1.0f, nullptr, nullptr);
    }

    // 5) out (fp32) = attnO (split) @ w_out (fp16)^T + b_out
    {
        auto kfn = hgemm<256, 256, 256, 256, 1024ll * 256, 0ll, 1024ll * 256,
                         AO_N, true, false, true, false, false>;
        cudaFuncSetAttribute(kfn, cudaFuncAttributeMaxDynamicSharedMemorySize, SMEM_BYTES);
        kfn<<<dim3(2, 8, 32), 256, SMEM_BYTES>>>(
            ao, wo, out, nullptr, nullptr, nullptr, nullptr, 1.0f, b_out, nullptr);
    }
}

// round 12
// speedup vs baseline: 1.9846x; 1.5522x over previous
#include <cuda_runtime.h>
#include <cuda_fp16.h>
#include <cstdint>

// ---------------- scratch (fp16, single plane) ----------------
#define XT_N (32ll * 1024 * 256)
#define QK_N (32ll * 1024 * 512)
#define VT_N (32ll * 256 * 1024)
#define P_N  (32ll * 1024 * 1024)
#define AO_N (32ll * 1024 * 256)
#define WQ_N (768ll * 256)
#define WO_N (256ll * 256)

__device__ __half g_xt[XT_N];
__device__ __half g_qk[QK_N];
__device__ __half g_vt[VT_N];
__device__ __half g_p [P_N];
__device__ __half g_ao[AO_N];
__device__ __half g_wq[WQ_N];
__device__ __half g_wo[WO_N];
__device__ float  g_scores[32ll * 1024 * 1024];

__device__ __forceinline__ uint32_t smem_u32(const void* p) {
    uint32_t a;
    asm("{ .reg .u64 t; cvta.to.shared.u64 t, %1; cvt.u32.u64 %0, t; }" : "=r"(a) : "l"(p));
    return a;
}

#define CP_ASYNC16(dst, src) \
    asm volatile("cp.async.cg.shared.global [%0], [%1], 16;" :: "r"(dst), "l"(src))
#define CP_COMMIT() asm volatile("cp.async.commit_group;")
#define CP_WAIT(n)  asm volatile("cp.async.wait_group %0;" :: "n"(n))

#define LDSM4(r0, r1, r2, r3, addr)                                               \
    asm volatile("ldmatrix.sync.aligned.m8n8.x4.shared.b16 {%0,%1,%2,%3}, [%4];"  \
                 : "=r"(r0), "=r"(r1), "=r"(r2), "=r"(r3) : "r"(addr))

#define MMA16816(c, a, b0, b1)                                                    \
    asm volatile("mma.sync.aligned.m16n8k16.row.col.f32.f16.f16.f32 "             \
                 "{%0,%1,%2,%3},{%4,%5,%6,%7},{%8,%9},{%0,%1,%2,%3};"             \
                 : "+f"((c)[0]), "+f"((c)[1]), "+f"((c)[2]), "+f"((c)[3])         \
                 : "r"((a)[0]), "r"((a)[1]), "r"((a)[2]), "r"((a)[3]),            \
                   "r"(b0), "r"(b1))

// Compact tile: 128 rows x 32 halves = 64 B/row, XOR-swizzled 16B chunks.
// Single-pass: A hi + B hi -> 2 tiles/stage.
#define TILE_B   8192
#define OFF_A    0
#define OFF_B    8192
#define BUF_B    16384
#define NSTAGE   3
#define SMEM_BYTES (NSTAGE * BUF_B)        // 49152 B

__device__ __forceinline__ uint32_t sws(int row, int khalf) {
    return (uint32_t)(row * 64 + ((((khalf >> 3) ^ (row >> 1)) & 3) << 4));
}

// C[128 x 128 tile] = A(m,k) . B(n,k)^T, fp16 inputs, fp32 accumulate.
template<int K, int LDA, int LDB, int LDC,
         long long SA, long long SB, long long SC,
         bool HAS_BIAS, bool HAS_MASK, bool OUT_F32, bool OUT_HALF, bool QKV>
__global__ __launch_bounds__(256, 2) void hgemm(
    const __half* __restrict__ Ah, const __half* __restrict__ Bh,
    float* __restrict__ C32, __half* __restrict__ Ch, __half* __restrict__ VTh,
    float alpha, const float* __restrict__ bias_n, const int* __restrict__ maskp)
{
    extern __shared__ char smem[];
    const uint32_t sbase = smem_u32(smem);
    const int tid = threadIdx.x;
    const int wid = tid >> 5, lane = tid & 31;
    const int bz = blockIdx.z;
    const int n0 = blockIdx.x * 128, m0 = blockIdx.y * 128;
    const int warp_m = wid & 1, warp_n = wid >> 1;   // 2 x 4 warp grid

    const __half* Ahb = Ah + bz * SA + (long long)m0 * LDA;
    const __half* Bhb = Bh + bz * SB + (long long)n0 * LDB;

    float acc[4][4][4];
#pragma unroll
    for (int mt = 0; mt < 4; mt++)
#pragma unroll
        for (int nt = 0; nt < 4; nt++)
#pragma unroll
            for (int r = 0; r < 4; r++) acc[mt][nt][r] = 0.f;

    // 2 tiles x 512 16B-granules / 256 threads = 4 cp per thread
    auto CP_TILES = [&](int ch, int buf) {
        const int k0 = ch << 5;
        const uint32_t sb = sbase + buf * BUF_B;
#pragma unroll
        for (int i = 0; i < 2; i++) {
            const int c = tid + i * 256;            // 0..511
            const int row = c >> 2, part = c & 3;
            const uint32_t doff = sws(row, part << 3);
            CP_ASYNC16(sb + OFF_A + doff, Ahb + (long long)row * LDA + k0 + part * 8);
            CP_ASYNC16(sb + OFF_B + doff, Bhb + (long long)row * LDB + k0 + part * 8);
        }
    };

    // lane-derived ldmatrix row/col bases
    const int a_row = warp_m * 64 + (lane & 7) + ((lane >> 3) & 1) * 8;
    const int a_kq  = (lane >> 4) * 8;
    const int b_row = warp_n * 32 + (lane >> 4) * 8 + (lane & 7);
    const int b_kq  = ((lane >> 3) & 1) * 8;

    auto COMPUTE = [&](int buf) {
        const uint32_t o = sbase + buf * BUF_B;
#pragma unroll
        for (int s = 0; s < 2; s++) {
            uint32_t bh[8];
#pragma unroll
            for (int p = 0; p < 2; p++) {
                const int row = b_row + p * 16;
                const uint32_t boff = sws(row, s * 16 + b_kq);
                LDSM4(bh[p * 4 + 0], bh[p * 4 + 1], bh[p * 4 + 2], bh[p * 4 + 3], o + OFF_B + boff);
            }
#pragma unroll
            for (int mt = 0; mt < 4; mt++) {
                uint32_t ah[4];
                const int row = a_row + mt * 16;
                const uint32_t aoff = sws(row, s * 16 + a_kq);
                LDSM4(ah[0], ah[1], ah[2], ah[3], o + OFF_A + aoff);
#pragma unroll
                for (int nt = 0; nt < 4; nt++) {
                    const int i0 = (nt >> 1) * 4 + (nt & 1) * 2;
                    MMA16816(acc[mt][nt], ah, bh[i0], bh[i0 + 1]);
                }
            }
        }
    };

    // 3-stage pipeline, one barrier per chunk
    constexpr int nch = K >> 5;
    CP_TILES(0, 0); CP_COMMIT();
    CP_TILES(1, 1); CP_COMMIT();
    int buf = 0, nxt = 2;
    for (int ch = 0; ch < nch; ch++) {
        if (ch + 1 < nch) { CP_WAIT(1); } else { CP_WAIT(0); }
        __syncthreads();
        if (ch + 2 < nch) {
            CP_TILES(ch + 2, nxt);
            CP_COMMIT();
        }
        COMPUTE(buf);
        buf = (buf + 1 == NSTAGE) ? 0 : buf + 1;
        nxt = (nxt + 1 == NSTAGE) ? 0 : nxt + 1;
    }

    // ---------------- epilogue ----------------
    const float NEG_INF = __int_as_float(0xff800000);
    const int gid = lane >> 2, q4 = lane & 3;
    const bool vmode = QKV && (n0 >= 512);

    if (!vmode) {
        float* C32b = OUT_F32 ? (C32 + bz * SC) : nullptr;
        __half* Chb = OUT_HALF ? (Ch + bz * SC) : nullptr;
        const int* mk = HAS_MASK ? (maskp + bz * SC) : nullptr;
#pragma unroll
        for (int mt = 0; mt < 4; mt++) {
#pragma unroll
            for (int nt = 0; nt < 4; nt++) {
                const int col = n0 + warp_n * 32 + nt * 8 + q4 * 2;
                float b0 = 0.f, b1 = 0.f;
                if (HAS_BIAS) { b0 = bias_n[col]; b1 = bias_n[col + 1]; }
#pragma unroll
                for (int h = 0; h < 2; h++) {
                    const int row = m0 + warp_m * 64 + mt * 16 + gid + h * 8;
                    float v0 = acc[mt][nt][h * 2 + 0] * alpha + b0;
                    float v1 = acc[mt][nt][h * 2 + 1] * alpha + b1;
                    if (HAS_MASK) {
                        int2 mv = *reinterpret_cast<const int2*>(mk + (long long)row * 1024 + col);
                        if (mv.x != 0) v0 = NEG_INF;
                        if (mv.y != 0) v1 = NEG_INF;
                    }
                    if (OUT_F32)
                        *reinterpret_cast<float2*>(C32b + (long long)row * LDC + col) =
                            make_float2(v0, v1);
                    if (OUT_HALF)
                        *reinterpret_cast<__half2*>(Chb + (long long)row * LDC + col) =
                            __floats2half2_rn(v0, v1);
                }
            }
        }
    } else {
        // V part of QKV: stage transposed in SMEM, then coalesced 16B stores.
        __syncthreads();
        __half* sh = reinterpret_cast<__half*>(smem);          // [128 d][136]
#pragma unroll
        for (int mt = 0; mt < 4; mt++) {
#pragma unroll
            for (int nt = 0; nt < 4; nt++) {
                const int cl0 = warp_n * 32 + nt * 8 + q4 * 2;
                const float b0 = bias_n[n0 + cl0];
                const float b1 = bias_n[n0 + cl0 + 1];
#pragma unroll
                for (int h = 0; h < 2; h++) {
                    const int rl = warp_m * 64 + mt * 16 + gid + h * 8;
                    sh[cl0 * 136 + rl] = __float2half_rn(acc[mt][nt][h * 2 + 0] + b0);
                    sh[(cl0 + 1) * 136 + rl] = __float2half_rn(acc[mt][nt][h * 2 + 1] + b1);
                }
            }
        }
        __syncthreads();
        __half* VThb = VTh + bz * (256ll * 1024);
#pragma unroll
        for (int i = tid; i < 128 * 16; i += 256) {
            const int d = i >> 4, seg = i & 15;
            uint4 uh = *reinterpret_cast<const uint4*>(&sh[d * 136 + seg * 8]);
            const long long o2 = (long long)(n0 - 512 + d) * 1024 + m0 + seg * 8;
            *reinterpret_cast<uint4*>(&VThb[o2]) = uh;
        }
    }
}

// ---------------- transpose x: (bc, 256, 1024) -> (bc, 1024, 256) fp16 ----------
__global__ __launch_bounds__(256) void transpose_kernel(
    const float* __restrict__ x, __half* __restrict__ xh)
{
    __shared__ float tile[32][33];
    const int bz = blockIdx.z;
    const float* xs = x + (long long)bz * 256 * 1024;
    __half* xhd = xh + (long long)bz * 1024 * 256;
    const int t0 = blockIdx.x * 32, d0 = blockIdx.y * 32;
    const int tx = threadIdx.x, ty = threadIdx.y;
#pragma unroll
    for (int k = 0; k < 4; k++)
        tile[ty + k * 8][tx] = xs[(long long)(d0 + ty + k * 8) * 1024 + t0 + tx];
    __syncthreads();
#pragma unroll
    for (int k = 0; k < 4; k++)
        xhd[(long long)(t0 + ty + k * 8) * 256 + d0 + tx] =
            __float2half_rn(tile[tx][ty + k * 8]);
}

// ---------------- weight fp32 -> fp16 ----------------
__global__ void cvt_kernel(const float* __restrict__ w, __half* __restrict__ h, int n)
{
    int i = blockIdx.x * 256 + threadIdx.x;
    if (i < n) h[i] = __float2half_rn(w[i]);
}

// ---------------- row softmax (fp32 in) -> P fp16 ----------------
__global__ __launch_bounds__(256) void softmax_kernel(
    const float* __restrict__ S, __half* __restrict__ Ph)
{
    const long long row = blockIdx.x;
    const float* p = S + row * 1024;
    const int tid = threadIdx.x;

    float4 v = reinterpret_cast<const float4*>(p)[tid];
    float m = fmaxf(fmaxf(v.x, v.y), fmaxf(v.z, v.w));
#pragma unroll
    for (int o = 16; o; o >>= 1) m = fmaxf(m, __shfl_xor_sync(0xffffffffu, m, o));

    __shared__ float red[8];
    if ((tid & 31) == 0) red[tid >> 5] = m;
    __syncthreads();
    float mm = red[0];
#pragma unroll
    for (int w = 1; w < 8; w++) mm = fmaxf(mm, red[w]);
    __syncthreads();

    float e0 = (v.x <= -1e30f) ? 0.f : __expf(v.x - mm);
    float e1 = (v.y <= -1e30f) ? 0.f : __expf(v.y - mm);
    float e2 = (v.z <= -1e30f) ? 0.f : __expf(v.z - mm);
    float e3 = (v.w <= -1e30f) ? 0.f : __expf(v.w - mm);

    float s = e0 + e1 + e2 + e3;
#pragma unroll
    for (int o = 16; o; o >>= 1) s += __shfl_xor_sync(0xffffffffu, s, o);
    if ((tid & 31) == 0) red[tid >> 5] = s;
    __syncthreads();
    float tot = red[0];
#pragma unroll
    for (int w = 1; w < 8; w++) tot += red[w];

    float inv = 1.0f / tot;
    __half2 h01 = __floats2half2_rn(e0 * inv, e1 * inv);
    __half2 h23 = __floats2half2_rn(e2 * inv, e3 * inv);
    *reinterpret_cast<uint2*>(Ph + row * 1024 + tid * 4) =
        make_uint2(*reinterpret_cast<uint32_t*>(&h01), *reinterpret_cast<uint32_t*>(&h23));
}

extern "C" void kernel_launch(void* const* d_in, const int* in_sizes, int n_in,
                              void* d_out, int out_size)
{
    const float* x     = (const float*)d_in[0];   // (8,4,256,1024)
    const int*   mask  = (const int*)d_in[1];     // (8,4,1024,1024) bool -> int32
    const float* w_qkv = (const float*)d_in[2];   // (768,256)
    const float* b_qkv = (const float*)d_in[3];   // (768,)
    const float* w_out = (const float*)d_in[4];   // (256,256)
    const float* b_out = (const float*)d_in[5];   // (256,)
    float*       out   = (float*)d_out;           // (8,4,1024,256)

    __half *xt, *qk, *vt, *pp, *ao, *wq, *wo;
    float* scores;
    cudaGetSymbolAddress((void**)&xt, g_xt);
    cudaGetSymbolAddress((void**)&qk, g_qk);
    cudaGetSymbolAddress((void**)&vt, g_vt);
    cudaGetSymbolAddress((void**)&pp, g_p);
    cudaGetSymbolAddress((void**)&ao, g_ao);
    cudaGetSymbolAddress((void**)&wq, g_wq);
    cudaGetSymbolAddress((void**)&wo, g_wo);
    cudaGetSymbolAddress((void**)&scores, g_scores);

    // 0) converters
    transpose_kernel<<<dim3(32, 8, 32), dim3(32, 8)>>>(x, xt);
    cvt_kernel<<<768, 256>>>(w_qkv, wq, 768 * 256);
    cvt_kernel<<<256, 256>>>(w_out, wo, 256 * 256);

    // 1) QKV: Q,K -> qk fp16; V -> vt fp16 (transposed)
    {
        auto kfn = hgemm<256, 256, 256, 512, 1024ll * 256, 0ll, 1024ll * 512,
                         true, false, false, true, true>;
        cudaFuncSetAttribute(kfn, cudaFuncAttributeMaxDynamicSharedMemorySize, SMEM_BYTES);
        kfn<<<dim3(6, 8, 32), 256, SMEM_BYTES>>>(
            xt, wq, nullptr, qk, vt, 1.0f, b_qkv, nullptr);
    }

    // 2) scores (fp32) = scale * Q @ K^T, mask -> -inf
    {
        auto kfn = hgemm<256, 512, 512, 1024, 1024ll * 512, 1024ll * 512, 1024ll * 1024,
                         false, true, true, false, false>;
        cudaFuncSetAttribute(kfn, cudaFuncAttributeMaxDynamicSharedMemorySize, SMEM_BYTES);
        kfn<<<dim3(8, 8, 32), 256, SMEM_BYTES>>>(
            qk, qk + 256, scores, nullptr, nullptr, 0.0625f, nullptr, mask);
    }

    // 3) softmax -> P fp16
    softmax_kernel<<<32 * 1024, 256>>>(scores, pp);

    // 4) attnO fp16 = P @ V
    {
        auto kfn = hgemm<1024, 1024, 1024, 256, 1024ll * 1024, 256ll * 1024, 1024ll * 256,
                         false, false, false, true, false>;
        cudaFuncSetAttribute(kfn, cudaFuncAttributeMaxDynamicSharedMemorySize, SMEM_BYTES);
        kfn<<<dim3(2, 8, 32), 256, SMEM_BYTES>>>(
            pp, vt, nullptr, ao, nullptr, 1.0f, nullptr, nullptr);
    }

    // 5) out (fp32) = attnO @ w_out^T + b_out
    {
        auto kfn = hgemm<256, 256, 256, 256, 1024ll * 256, 0ll, 1024ll * 256,
                         true, false, true, false, false>;
        cudaFuncSetAttribute(kfn, cudaFuncAttributeMaxDynamicSharedMemorySize, SMEM_BYTES);
        kfn<<<dim3(2, 8, 32), 256, SMEM_BYTES>>>(
            ao, wo, out, nullptr, nullptr, 1.0f, b_out, nullptr);
    }
}

// round 13
// speedup vs baseline: 2.1539x; 1.0853x over previous
#include <cuda_runtime.h>
#include <cuda_fp16.h>
#include <cstdint>

// ---------------- scratch (fp16, single plane) ----------------
#define XT_N (32ll * 1024 * 256)
#define QK_N (32ll * 1024 * 512)
#define VT_N (32ll * 256 * 1024)
#define E_N  (32ll * 1024 * 1024)
#define AO_N (32ll * 1024 * 256)
#define WQ_N (768ll * 256)
#define WO_N (256ll * 256)

__device__ __half g_xt[XT_N];
__device__ __half g_qk[QK_N];
__device__ __half g_vt[VT_N];
__device__ __half g_e [E_N];                 // exp(scores), unnormalized
__device__ __half g_ao[AO_N];
__device__ __half g_wq[WQ_N];
__device__ __half g_wo[WO_N];
__device__ float  g_inv[32ll * 1024];        // 1 / rowsum

__device__ __forceinline__ uint32_t smem_u32(const void* p) {
    uint32_t a;
    asm("{ .reg .u64 t; cvta.to.shared.u64 t, %1; cvt.u32.u64 %0, t; }" : "=r"(a) : "l"(p));
    return a;
}

#define CP_ASYNC16(dst, src) \
    asm volatile("cp.async.cg.shared.global [%0], [%1], 16;" :: "r"(dst), "l"(src))
#define CP_COMMIT() asm volatile("cp.async.commit_group;")
#define CP_WAIT(n)  asm volatile("cp.async.wait_group %0;" :: "n"(n))

#define LDSM4(r0, r1, r2, r3, addr)                                               \
    asm volatile("ldmatrix.sync.aligned.m8n8.x4.shared.b16 {%0,%1,%2,%3}, [%4];"  \
                 : "=r"(r0), "=r"(r1), "=r"(r2), "=r"(r3) : "r"(addr))

#define MMA16816(c, a, b0, b1)                                                    \
    asm volatile("mma.sync.aligned.m16n8k16.row.col.f32.f16.f16.f32 "             \
                 "{%0,%1,%2,%3},{%4,%5,%6,%7},{%8,%9},{%0,%1,%2,%3};"             \
                 : "+f"((c)[0]), "+f"((c)[1]), "+f"((c)[2]), "+f"((c)[3])         \
                 : "r"((a)[0]), "r"((a)[1]), "r"((a)[2]), "r"((a)[3]),            \
                   "r"(b0), "r"(b1))

// Compact tile: 128 rows x 32 halves = 64 B/row, XOR-swizzled 16B chunks.
#define TILE_B   8192
#define OFF_A    0
#define OFF_B    8192
#define BUF_B    16384
#define NSTAGE   3
#define SMEM_BYTES (NSTAGE * BUF_B)        // 49152 B

__device__ __forceinline__ uint32_t sws(int row, int khalf) {
    return (uint32_t)(row * 64 + ((((khalf >> 3) ^ (row >> 1)) & 3) << 4));
}

// C[128 x 128 tile] = A(m,k) . B(n,k)^T, fp16 inputs, fp32 accumulate.
// OUT_EXP: write fp16 exp(v) (mask -> 0).  SCALE_M: multiply by scale_m[row].
template<int K, int LDA, int LDB, int LDC,
         long long SA, long long SB, long long SC,
         bool HAS_BIAS, bool HAS_MASK, bool OUT_F32, bool OUT_HALF,
         bool OUT_EXP, bool SCALE_M, bool QKV>
__global__ __launch_bounds__(256, 2) void hgemm(
    const __half* __restrict__ Ah, const __half* __restrict__ Bh,
    float* __restrict__ C32, __half* __restrict__ Ch, __half* __restrict__ VTh,
    float alpha, const float* __restrict__ bias_n, const int* __restrict__ maskp,
    const float* __restrict__ scale_m)
{
    extern __shared__ char smem[];
    const uint32_t sbase = smem_u32(smem);
    const int tid = threadIdx.x;
    const int wid = tid >> 5, lane = tid & 31;
    const int bz = blockIdx.z;
    const int n0 = blockIdx.x * 128, m0 = blockIdx.y * 128;
    const int warp_m = wid & 1, warp_n = wid >> 1;   // 2 x 4 warp grid

    const __half* Ahb = Ah + bz * SA + (long long)m0 * LDA;
    const __half* Bhb = Bh + bz * SB + (long long)n0 * LDB;

    float acc[4][4][4];
#pragma unroll
    for (int mt = 0; mt < 4; mt++)
#pragma unroll
        for (int nt = 0; nt < 4; nt++)
#pragma unroll
            for (int r = 0; r < 4; r++) acc[mt][nt][r] = 0.f;

    auto CP_TILES = [&](int ch, int buf) {
        const int k0 = ch << 5;
        const uint32_t sb = sbase + buf * BUF_B;
#pragma unroll
        for (int i = 0; i < 2; i++) {
            const int c = tid + i * 256;            // 0..511
            const int row = c >> 2, part = c & 3;
            const uint32_t doff = sws(row, part << 3);
            CP_ASYNC16(sb + OFF_A + doff, Ahb + (long long)row * LDA + k0 + part * 8);
            CP_ASYNC16(sb + OFF_B + doff, Bhb + (long long)row * LDB + k0 + part * 8);
        }
    };

    const int a_row = warp_m * 64 + (lane & 7) + ((lane >> 3) & 1) * 8;
    const int a_kq  = (lane >> 4) * 8;
    const int b_row = warp_n * 32 + (lane >> 4) * 8 + (lane & 7);
    const int b_kq  = ((lane >> 3) & 1) * 8;

    auto COMPUTE = [&](int buf) {
        const uint32_t o = sbase + buf * BUF_B;
#pragma unroll
        for (int s = 0; s < 2; s++) {
            uint32_t bh[8];
#pragma unroll
            for (int p = 0; p < 2; p++) {
                const int row = b_row + p * 16;
                const uint32_t boff = sws(row, s * 16 + b_kq);
                LDSM4(bh[p * 4 + 0], bh[p * 4 + 1], bh[p * 4 + 2], bh[p * 4 + 3], o + OFF_B + boff);
            }
#pragma unroll
            for (int mt = 0; mt < 4; mt++) {
                uint32_t ah[4];
                const int row = a_row + mt * 16;
                const uint32_t aoff = sws(row, s * 16 + a_kq);
                LDSM4(ah[0], ah[1], ah[2], ah[3], o + OFF_A + aoff);
#pragma unroll
                for (int nt = 0; nt < 4; nt++) {
                    const int i0 = (nt >> 1) * 4 + (nt & 1) * 2;
                    MMA16816(acc[mt][nt], ah, bh[i0], bh[i0 + 1]);
                }
            }
        }
    };

    constexpr int nch = K >> 5;
    CP_TILES(0, 0); CP_COMMIT();
    CP_TILES(1, 1); CP_COMMIT();
    int buf = 0, nxt = 2;
    for (int ch = 0; ch < nch; ch++) {
        if (ch + 1 < nch) { CP_WAIT(1); } else { CP_WAIT(0); }
        __syncthreads();
        if (ch + 2 < nch) {
            CP_TILES(ch + 2, nxt);
            CP_COMMIT();
        }
        COMPUTE(buf);
        buf = (buf + 1 == NSTAGE) ? 0 : buf + 1;
        nxt = (nxt + 1 == NSTAGE) ? 0 : nxt + 1;
    }

    // ---------------- epilogue ----------------
    const float NEG_INF = __int_as_float(0xff800000);
    const int gid = lane >> 2, q4 = lane & 3;
    const bool vmode = QKV && (n0 >= 512);

    if (!vmode) {
        float* C32b = OUT_F32 ? (C32 + bz * SC) : nullptr;
        __half* Chb = OUT_HALF ? (Ch + bz * SC) : nullptr;
        const int* mk = HAS_MASK ? (maskp + bz * SC) : nullptr;
        const float* smr = SCALE_M ? (scale_m + (long long)bz * 1024) : nullptr;
#pragma unroll
        for (int mt = 0; mt < 4; mt++) {
#pragma unroll
            for (int nt = 0; nt < 4; nt++) {
                const int col = n0 + warp_n * 32 + nt * 8 + q4 * 2;
                float b0 = 0.f, b1 = 0.f;
                if (HAS_BIAS) { b0 = bias_n[col]; b1 = bias_n[col + 1]; }
#pragma unroll
                for (int h = 0; h < 2; h++) {
                    const int row = m0 + warp_m * 64 + mt * 16 + gid + h * 8;
                    float v0 = acc[mt][nt][h * 2 + 0] * alpha + b0;
                    float v1 = acc[mt][nt][h * 2 + 1] * alpha + b1;
                    if (HAS_MASK) {
                        int2 mv = *reinterpret_cast<const int2*>(mk + (long long)row * 1024 + col);
                        if (mv.x != 0) v0 = NEG_INF;
                        if (mv.y != 0) v1 = NEG_INF;
                    }
                    if (OUT_EXP) {            // exp(-inf) -> 0 handles the mask
                        v0 = __expf(v0);
                        v1 = __expf(v1);
                    }
                    if (SCALE_M) {
                        const float sm = smr[row];
                        v0 *= sm; v1 *= sm;
                    }
                    if (OUT_F32)
                        *reinterpret_cast<float2*>(C32b + (long long)row * LDC + col) =
                            make_float2(v0, v1);
                    if (OUT_HALF)
                        *reinterpret_cast<__half2*>(Chb + (long long)row * LDC + col) =
                            __floats2half2_rn(v0, v1);
                }
            }
        }
    } else {
        // V part of QKV: stage transposed in SMEM, then coalesced 16B stores.
        __syncthreads();
        __half* sh = reinterpret_cast<__half*>(smem);          // [128 d][136]
#pragma unroll
        for (int mt = 0; mt < 4; mt++) {
#pragma unroll
            for (int nt = 0; nt < 4; nt++) {
                const int cl0 = warp_n * 32 + nt * 8 + q4 * 2;
                const float b0 = bias_n[n0 + cl0];
                const float b1 = bias_n[n0 + cl0 + 1];
#pragma unroll
                for (int h = 0; h < 2; h++) {
                    const int rl = warp_m * 64 + mt * 16 + gid + h * 8;
                    sh[cl0 * 136 + rl] = __float2half_rn(acc[mt][nt][h * 2 + 0] + b0);
                    sh[(cl0 + 1) * 136 + rl] = __float2half_rn(acc[mt][nt][h * 2 + 1] + b1);
                }
            }
        }
        __syncthreads();
        __half* VThb = VTh + bz * (256ll * 1024);
#pragma unroll
        for (int i = tid; i < 128 * 16; i += 256) {
            const int d = i >> 4, seg = i & 15;
            uint4 uh = *reinterpret_cast<const uint4*>(&sh[d * 136 + seg * 8]);
            const long long o2 = (long long)(n0 - 512 + d) * 1024 + m0 + seg * 8;
            *reinterpret_cast<uint4*>(&VThb[o2]) = uh;
        }
    }
}

// ---------------- transpose x: (bc, 256, 1024) -> (bc, 1024, 256) fp16 ----------
__global__ __launch_bounds__(256) void transpose_kernel(
    const float* __restrict__ x, __half* __restrict__ xh)
{
    __shared__ float tile[32][33];
    const int bz = blockIdx.z;
    const float* xs = x + (long long)bz * 256 * 1024;
    __half* xhd = xh + (long long)bz * 1024 * 256;
    const int t0 = blockIdx.x * 32, d0 = blockIdx.y * 32;
    const int tx = threadIdx.x, ty = threadIdx.y;
#pragma unroll
    for (int k = 0; k < 4; k++)
        tile[ty + k * 8][tx] = xs[(long long)(d0 + ty + k * 8) * 1024 + t0 + tx];
    __syncthreads();
#pragma unroll
    for (int k = 0; k < 4; k++)
        xhd[(long long)(t0 + ty + k * 8) * 256 + d0 + tx] =
            __float2half_rn(tile[tx][ty + k * 8]);
}

// ---------------- weight fp32 -> fp16 ----------------
__global__ void cvt_kernel(const float* __restrict__ w, __half* __restrict__ h, int n)
{
    int i = blockIdx.x * 256 + threadIdx.x;
    if (i < n) h[i] = __float2half_rn(w[i]);
}

// ---------------- rowsum of E (fp16) -> inv = 1/sum (fp32) ----------------
__global__ __launch_bounds__(256) void rowsum_kernel(
    const __half* __restrict__ E, float* __restrict__ inv)
{
    const long long row = blockIdx.x;
    const int tid = threadIdx.x;
    // 1024 halves per row; 256 threads x 4 halves (uint2)
    uint2 u = *reinterpret_cast<const uint2*>(E + row * 1024 + tid * 4);
    float2 a = __half22float2(*reinterpret_cast<__half2*>(&u.x));
    float2 b = __half22float2(*reinterpret_cast<__half2*>(&u.y));
    float s = a.x + a.y + b.x + b.y;
#pragma unroll
    for (int o = 16; o; o >>= 1) s += __shfl_xor_sync(0xffffffffu, s, o);
    __shared__ float red[8];
    if ((tid & 31) == 0) red[tid >> 5] = s;
    __syncthreads();
    if (tid == 0) {
        float tot = red[0];
#pragma unroll
        for (int w = 1; w < 8; w++) tot += red[w];
        inv[row] = 1.0f / tot;
    }
}

extern "C" void kernel_launch(void* const* d_in, const int* in_sizes, int n_in,
                              void* d_out, int out_size)
{
    const float* x     = (const float*)d_in[0];   // (8,4,256,1024)
    const int*   mask  = (const int*)d_in[1];     // (8,4,1024,1024) bool -> int32
    const float* w_qkv = (const float*)d_in[2];   // (768,256)
    const float* b_qkv = (const float*)d_in[3];   // (768,)
    const float* w_out = (const float*)d_in[4];   // (256,256)
    const float* b_out = (const float*)d_in[5];   // (256,)
    float*       out   = (float*)d_out;           // (8,4,1024,256)

    __half *xt, *qk, *vt, *ee, *ao, *wq, *wo;
    float* inv;
    cudaGetSymbolAddress((void**)&xt, g_xt);
    cudaGetSymbolAddress((void**)&qk, g_qk);
    cudaGetSymbolAddress((void**)&vt, g_vt);
    cudaGetSymbolAddress((void**)&ee, g_e);
    cudaGetSymbolAddress((void**)&ao, g_ao);
    cudaGetSymbolAddress((void**)&wq, g_wq);
    cudaGetSymbolAddress((void**)&wo, g_wo);
    cudaGetSymbolAddress((void**)&inv, g_inv);

    // 0) converters
    transpose_kernel<<<dim3(32, 8, 32), dim3(32, 8)>>>(x, xt);
    cvt_kernel<<<768, 256>>>(w_qkv, wq, 768 * 256);
    cvt_kernel<<<256, 256>>>(w_out, wo, 256 * 256);

    // 1) QKV: Q,K -> qk fp16; V -> vt fp16 (transposed)
    {
        auto kfn = hgemm<256, 256, 256, 512, 1024ll * 256, 0ll, 1024ll * 512,
                         true, false, false, true, false, false, true>;
        cudaFuncSetAttribute(kfn, cudaFuncAttributeMaxDynamicSharedMemorySize, SMEM_BYTES);
        kfn<<<dim3(6, 8, 32), 256, SMEM_BYTES>>>(
            xt, wq, nullptr, qk, vt, 1.0f, b_qkv, nullptr, nullptr);
    }

    // 2) E (fp16) = exp(scale * Q @ K^T), masked -> 0
    {
        auto kfn = hgemm<256, 512, 512, 1024, 1024ll * 512, 1024ll * 512, 1024ll * 1024,
                         false, true, false, true, true, false, false>;
        cudaFuncSetAttribute(kfn, cudaFuncAttributeMaxDynamicSharedMemorySize, SMEM_BYTES);
        kfn<<<dim3(8, 8, 32), 256, SMEM_BYTES>>>(
            qk, qk + 256, nullptr, ee, nullptr, 0.0625f, nullptr, mask, nullptr);
    }

    // 3) inv rowsum
    rowsum_kernel<<<32 * 1024, 256>>>(ee, inv);

    // 4) attnO fp16 = (E @ V) * inv[row]
    {
        auto kfn = hgemm<1024, 1024, 1024, 256, 1024ll * 1024, 256ll * 1024, 1024ll * 256,
                         false, false, false, true, false, true, false>;
        cudaFuncSetAttribute(kfn, cudaFuncAttributeMaxDynamicSharedMemorySize, SMEM_BYTES);
        kfn<<<dim3(2, 8, 32), 256, SMEM_BYTES>>>(
            ee, vt, nullptr, ao, nullptr, 1.0f, nullptr, nullptr, inv);
    }

    // 5) out (fp32) = attnO @ w_out^T + b_out
    {
        auto kfn = hgemm<256, 256, 256, 256, 1024ll * 256, 0ll, 1024ll * 256,
                         true, false, true, false, false, false, false>;
        cudaFuncSetAttribute(kfn, cudaFuncAttributeMaxDynamicSharedMemorySize, SMEM_BYTES);
        kfn<<<dim3(2, 8, 32), 256, SMEM_BYTES>>>(
            ao, wo, out, nullptr, nullptr, 1.0f, b_out, nullptr, nullptr);
    }
}

// round 14
// speedup vs baseline: 2.2111x; 1.0265x over previous
#include <cuda_runtime.h>
#include <cuda_fp16.h>
#include <cstdint>

// ---------------- scratch (fp16, single plane) ----------------
#define XT_N (32ll * 1024 * 256)
#define QK_N (32ll * 1024 * 512)
#define VT_N (32ll * 256 * 1024)
#define AO_N (32ll * 1024 * 256)
#define WQ_N (768ll * 256)
#define WO_N (256ll * 256)

__device__ __half g_xt[XT_N];
__device__ __half g_qk[QK_N];
__device__ __half g_vt[VT_N];
__device__ __half g_ao[AO_N];
__device__ __half g_wq[WQ_N];
__device__ __half g_wo[WO_N];

__device__ __forceinline__ uint32_t smem_u32(const void* p) {
    uint32_t a;
    asm("{ .reg .u64 t; cvta.to.shared.u64 t, %1; cvt.u32.u64 %0, t; }" : "=r"(a) : "l"(p));
    return a;
}

#define CP_ASYNC16(dst, src) \
    asm volatile("cp.async.cg.shared.global [%0], [%1], 16;" :: "r"(dst), "l"(src))
#define CP_COMMIT() asm volatile("cp.async.commit_group;")
#define CP_WAIT(n)  asm volatile("cp.async.wait_group %0;" :: "n"(n))

#define LDSM4(r0, r1, r2, r3, addr)                                               \
    asm volatile("ldmatrix.sync.aligned.m8n8.x4.shared.b16 {%0,%1,%2,%3}, [%4];"  \
                 : "=r"(r0), "=r"(r1), "=r"(r2), "=r"(r3) : "r"(addr))

#define MMA16816(c, a, b0, b1)                                                    \
    asm volatile("mma.sync.aligned.m16n8k16.row.col.f32.f16.f16.f32 "             \
                 "{%0,%1,%2,%3},{%4,%5,%6,%7},{%8,%9},{%0,%1,%2,%3};"             \
                 : "+f"((c)[0]), "+f"((c)[1]), "+f"((c)[2]), "+f"((c)[3])         \
                 : "r"((a)[0]), "r"((a)[1]), "r"((a)[2]), "r"((a)[3]),            \
                   "r"(b0), "r"(b1))

// Tile chunks: rows x 32 halves = 64 B/row, XOR-swizzled 16B granules.
__device__ __forceinline__ uint32_t sws(int row, int khalf) {
    return (uint32_t)(row * 64 + ((((khalf >> 3) ^ (row >> 1)) & 3) << 4));
}

// ======================= generic hgemm (QKV / out-proj) =======================
#define TILE_B   8192
#define OFF_A    0
#define OFF_B    8192
#define BUF_B    16384
#define NSTAGE   3
#define SMEM_BYTES (NSTAGE * BUF_B)        // 49152 B

template<int K, int LDA, int LDB, int LDC,
         long long SA, long long SB, long long SC,
         bool HAS_BIAS, bool OUT_F32, bool OUT_HALF, bool QKV>
__global__ __launch_bounds__(256, 2) void hgemm(
    const __half* __restrict__ Ah, const __half* __restrict__ Bh,
    float* __restrict__ C32, __half* __restrict__ Ch, __half* __restrict__ VTh,
    const float* __restrict__ bias_n)
{
    extern __shared__ char smem[];
    const uint32_t sbase = smem_u32(smem);
    const int tid = threadIdx.x;
    const int wid = tid >> 5, lane = tid & 31;
    const int bz = blockIdx.z;
    const int n0 = blockIdx.x * 128, m0 = blockIdx.y * 128;
    const int warp_m = wid & 1, warp_n = wid >> 1;

    const __half* Ahb = Ah + bz * SA + (long long)m0 * LDA;
    const __half* Bhb = Bh + bz * SB + (long long)n0 * LDB;

    float acc[4][4][4];
#pragma unroll
    for (int mt = 0; mt < 4; mt++)
#pragma unroll
        for (int nt = 0; nt < 4; nt++)
#pragma unroll
            for (int r = 0; r < 4; r++) acc[mt][nt][r] = 0.f;

    auto CP_TILES = [&](int ch, int buf) {
        const int k0 = ch << 5;
        const uint32_t sb = sbase + buf * BUF_B;
#pragma unroll
        for (int i = 0; i < 2; i++) {
            const int c = tid + i * 256;
            const int row = c >> 2, part = c & 3;
            const uint32_t doff = sws(row, part << 3);
            CP_ASYNC16(sb + OFF_A + doff, Ahb + (long long)row * LDA + k0 + part * 8);
            CP_ASYNC16(sb + OFF_B + doff, Bhb + (long long)row * LDB + k0 + part * 8);
        }
    };

    const int a_row = warp_m * 64 + (lane & 7) + ((lane >> 3) & 1) * 8;
    const int a_kq  = (lane >> 4) * 8;
    const int b_row = warp_n * 32 + (lane >> 4) * 8 + (lane & 7);
    const int b_kq  = ((lane >> 3) & 1) * 8;

    auto COMPUTE = [&](int buf) {
        const uint32_t o = sbase + buf * BUF_B;
#pragma unroll
        for (int s = 0; s < 2; s++) {
            uint32_t bh[8];
#pragma unroll
            for (int p = 0; p < 2; p++) {
                const int row = b_row + p * 16;
                LDSM4(bh[p * 4 + 0], bh[p * 4 + 1], bh[p * 4 + 2], bh[p * 4 + 3],
                      o + OFF_B + sws(row, s * 16 + b_kq));
            }
#pragma unroll
            for (int mt = 0; mt < 4; mt++) {
                uint32_t ah[4];
                LDSM4(ah[0], ah[1], ah[2], ah[3],
                      o + OFF_A + sws(a_row + mt * 16, s * 16 + a_kq));
#pragma unroll
                for (int nt = 0; nt < 4; nt++) {
                    const int i0 = (nt >> 1) * 4 + (nt & 1) * 2;
                    MMA16816(acc[mt][nt], ah, bh[i0], bh[i0 + 1]);
                }
            }
        }
    };

    constexpr int nch = K >> 5;
    CP_TILES(0, 0); CP_COMMIT();
    CP_TILES(1, 1); CP_COMMIT();
    int buf = 0, nxt = 2;
    for (int ch = 0; ch < nch; ch++) {
        if (ch + 1 < nch) { CP_WAIT(1); } else { CP_WAIT(0); }
        __syncthreads();
        if (ch + 2 < nch) {
            CP_TILES(ch + 2, nxt);
            CP_COMMIT();
        }
        COMPUTE(buf);
        buf = (buf + 1 == NSTAGE) ? 0 : buf + 1;
        nxt = (nxt + 1 == NSTAGE) ? 0 : nxt + 1;
    }

    const int gid = lane >> 2, q4 = lane & 3;
    const bool vmode = QKV && (n0 >= 512);

    if (!vmode) {
        float* C32b = OUT_F32 ? (C32 + bz * SC) : nullptr;
        __half* Chb = OUT_HALF ? (Ch + bz * SC) : nullptr;
#pragma unroll
        for (int mt = 0; mt < 4; mt++) {
#pragma unroll
            for (int nt = 0; nt < 4; nt++) {
                const int col = n0 + warp_n * 32 + nt * 8 + q4 * 2;
                float b0 = 0.f, b1 = 0.f;
                if (HAS_BIAS) { b0 = bias_n[col]; b1 = bias_n[col + 1]; }
#pragma unroll
                for (int h = 0; h < 2; h++) {
                    const int row = m0 + warp_m * 64 + mt * 16 + gid + h * 8;
                    float v0 = acc[mt][nt][h * 2 + 0] + b0;
                    float v1 = acc[mt][nt][h * 2 + 1] + b1;
                    if (OUT_F32)
                        *reinterpret_cast<float2*>(C32b + (long long)row * LDC + col) =
                            make_float2(v0, v1);
                    if (OUT_HALF)
                        *reinterpret_cast<__half2*>(Chb + (long long)row * LDC + col) =
                            __floats2half2_rn(v0, v1);
                }
            }
        }
    } else {
        __syncthreads();
        __half* sh = reinterpret_cast<__half*>(smem);          // [128 d][136]
#pragma unroll
        for (int mt = 0; mt < 4; mt++) {
#pragma unroll
            for (int nt = 0; nt < 4; nt++) {
                const int cl0 = warp_n * 32 + nt * 8 + q4 * 2;
                const float b0 = bias_n[n0 + cl0];
                const float b1 = bias_n[n0 + cl0 + 1];
#pragma unroll
                for (int h = 0; h < 2; h++) {
                    const int rl = warp_m * 64 + mt * 16 + gid + h * 8;
                    sh[cl0 * 136 + rl] = __float2half_rn(acc[mt][nt][h * 2 + 0] + b0);
                    sh[(cl0 + 1) * 136 + rl] = __float2half_rn(acc[mt][nt][h * 2 + 1] + b1);
                }
            }
        }
        __syncthreads();
        __half* VThb = VTh + bz * (256ll * 1024);
#pragma unroll
        for (int i = tid; i < 128 * 16; i += 256) {
            const int d = i >> 4, seg = i & 15;
            uint4 uh = *reinterpret_cast<const uint4*>(&sh[d * 136 + seg * 8]);
            const long long o2 = (long long)(n0 - 512 + d) * 1024 + m0 + seg * 8;
            *reinterpret_cast<uint4*>(&VThb[o2]) = uh;
        }
    }
}

// ======================= fused attention: S = QK^T, exp, O = E V, /rowsum ==========
// CTA = 128 queries; 8 warps x 16 q-rows. Q resident in SMEM (64KB);
// K/V streamed in 64-key tiles, double-buffered (2 x 64KB). 1 CTA/SM.
#define ATT_Q_OFF   0
#define ATT_STG_OFF 65536
#define ATT_STG_B   65536
#define ATT_SMEM    (65536 + 2 * 65536)   // 196608

__global__ __launch_bounds__(256, 1) void attn_kernel(
    const __half* __restrict__ qk,   // (bc, 1024, 512): Q cols 0..255, K cols 256..511
    const __half* __restrict__ vt,   // (bc, 256, 1024)
    __half* __restrict__ ao,         // (bc, 1024, 256)
    const int* __restrict__ mask)    // (bc, 1024, 1024)
{
    extern __shared__ char smem[];
    const uint32_t sb = smem_u32(smem);
    const int tid = threadIdx.x, wq = tid >> 5, lane = tid & 31;
    const int qt = blockIdx.x, bz = blockIdx.y;
    const int gid = lane >> 2, q4 = lane & 3;

    const __half* qkb = qk + (long long)bz * 524288;
    const __half* vtb = vt + (long long)bz * 262144;
    const int* mkb = mask + (long long)bz * 1048576;

    // ---- Q load: 8 d-chunks x (128 rows x 32 halves) ----
#pragma unroll
    for (int i = 0; i < 16; i++) {
        const int g = tid + i * 256;
        const int ch = g >> 9, rem = g & 511, row = rem >> 2, part = rem & 3;
        CP_ASYNC16(sb + ATT_Q_OFF + ch * 8192 + sws(row, part * 8),
                   qkb + (long long)(qt * 128 + row) * 512 + ch * 32 + part * 8);
    }

    // K tile: 8 d-chunks x (64 rows x 32 halves) at +0; V tile: 2 t-chunks x (256 x 32) at +32768
    auto LOAD_KV = [&](int kt, int stg) {
        const uint32_t so = sb + ATT_STG_OFF + stg * ATT_STG_B;
#pragma unroll
        for (int i = 0; i < 16; i++) {
            const int g = tid + i * 256;
            if (g < 2048) {
                const int ch = g >> 8, rem = g & 255, row = rem >> 2, part = rem & 3;
                CP_ASYNC16(so + ch * 4096 + sws(row, part * 8),
                           qkb + (long long)(kt * 64 + row) * 512 + 256 + ch * 32 + part * 8);
            } else {
                const int g2 = g - 2048;
                const int tc = g2 >> 10, rem = g2 & 1023, row = rem >> 2, part = rem & 3;
                CP_ASYNC16(so + 32768 + tc * 16384 + sws(row, part * 8),
                           vtb + (long long)row * 1024 + kt * 64 + tc * 32 + part * 8);
            }
        }
    };
    LOAD_KV(0, 0); CP_COMMIT();      // group includes Q
    LOAD_KV(1, 1); CP_COMMIT();

    float O[32][4];
#pragma unroll
    for (int i = 0; i < 32; i++)
#pragma unroll
        for (int j = 0; j < 4; j++) O[i][j] = 0.f;
    float rs0 = 0.f, rs1 = 0.f;

    const int arow = wq * 16 + (lane & 7) + ((lane >> 3) & 1) * 8;
    const int akq  = (lane >> 4) * 8;
    const int brow8 = (lane >> 4) * 8 + (lane & 7);
    const int bkq  = ((lane >> 3) & 1) * 8;
    const long long mrow0 = (long long)(qt * 128 + wq * 16 + gid) * 1024;

    for (int kt = 0; kt < 16; kt++) {
        if (kt + 1 < 16) { CP_WAIT(1); } else { CP_WAIT(0); }
        __syncthreads();
        const uint32_t so = sb + ATT_STG_OFF + (kt & 1) * ATT_STG_B;

#pragma unroll
        for (int ks = 0; ks < 2; ks++) {
            // mask prefetch (independent of MMAs below -> latency hidden)
            int2 mv[8];
            const int kb0 = kt * 64 + ks * 32;
#pragma unroll
            for (int nt = 0; nt < 4; nt++) {
                const int col = kb0 + nt * 8 + q4 * 2;
                mv[nt * 2]     = *reinterpret_cast<const int2*>(mkb + mrow0 + col);
                mv[nt * 2 + 1] = *reinterpret_cast<const int2*>(mkb + mrow0 + 8192 + col);
            }
            // S = Q . K^T  (16 q x 32 k per warp)
            float s[4][4];
#pragma unroll
            for (int nt = 0; nt < 4; nt++)
#pragma unroll
                for (int j = 0; j < 4; j++) s[nt][j] = 0.f;
#pragma unroll
            for (int dch = 0; dch < 8; dch++) {
#pragma unroll
                for (int st = 0; st < 2; st++) {
                    uint32_t aq[4];
                    LDSM4(aq[0], aq[1], aq[2], aq[3],
                          sb + ATT_Q_OFF + dch * 8192 + sws(arow, st * 16 + akq));
                    uint32_t bh[8];
#pragma unroll
                    for (int kb = 0; kb < 2; kb++) {
                        const int krow = ks * 32 + kb * 16 + brow8;
                        LDSM4(bh[kb * 4], bh[kb * 4 + 1], bh[kb * 4 + 2], bh[kb * 4 + 3],
                              so + dch * 4096 + sws(krow, st * 16 + bkq));
                    }
#pragma unroll
                    for (int nt = 0; nt < 4; nt++) {
                        const int i0 = (nt >> 1) * 4 + (nt & 1) * 2;
                        MMA16816(s[nt], aq, bh[i0], bh[i0 + 1]);
                    }
                }
            }
            // mask -> exp -> rowsum -> repack to A-fragments
            uint32_t eA[2][4];
#pragma unroll
            for (int half = 0; half < 2; half++) {
#pragma unroll
                for (int j = 0; j < 2; j++) {
                    const int nt = half * 2 + j;
                    const float e0 = mv[nt * 2].x     ? 0.f : __expf(s[nt][0] * 0.0625f);
                    const float e1 = mv[nt * 2].y     ? 0.f : __expf(s[nt][1] * 0.0625f);
                    const float e2 = mv[nt * 2 + 1].x ? 0.f : __expf(s[nt][2] * 0.0625f);
                    const float e3 = mv[nt * 2 + 1].y ? 0.f : __expf(s[nt][3] * 0.0625f);
                    rs0 += e0 + e1;
                    rs1 += e2 + e3;
                    __half2 h01 = __floats2half2_rn(e0, e1);
                    __half2 h23 = __floats2half2_rn(e2, e3);
                    eA[half][j * 2]     = *reinterpret_cast<uint32_t*>(&h01);
                    eA[half][j * 2 + 1] = *reinterpret_cast<uint32_t*>(&h23);
                }
            }
            // O += E . V   (16 q x 256 d, k = 32 keys)
#pragma unroll
            for (int dblk = 0; dblk < 16; dblk++) {
#pragma unroll
                for (int kstep = 0; kstep < 2; kstep++) {
                    uint32_t bv[4];
                    LDSM4(bv[0], bv[1], bv[2], bv[3],
                          so + 32768 + ks * 16384 + sws(dblk * 16 + brow8, kstep * 16 + bkq));
                    MMA16816(O[dblk * 2],     eA[kstep], bv[0], bv[1]);
                    MMA16816(O[dblk * 2 + 1], eA[kstep], bv[2], bv[3]);
                }
            }
        }
        __syncthreads();
        if (kt + 2 < 16) { LOAD_KV(kt + 2, kt & 1); CP_COMMIT(); }
    }

    // ---- epilogue: rowsum reduce, normalize, store fp16 ----
    rs0 += __shfl_xor_sync(0xffffffffu, rs0, 1);
    rs0 += __shfl_xor_sync(0xffffffffu, rs0, 2);
    rs1 += __shfl_xor_sync(0xffffffffu, rs1, 1);
    rs1 += __shfl_xor_sync(0xffffffffu, rs1, 2);
    const float inv0 = __frcp_rn(rs0), inv1 = __frcp_rn(rs1);

    __half* aob = ao + (long long)bz * 262144 + (long long)(qt * 128 + wq * 16 + gid) * 256;
#pragma unroll
    for (int nt = 0; nt < 32; nt++) {
        const int col = nt * 8 + q4 * 2;
        *reinterpret_cast<__half2*>(aob + col) =
            __floats2half2_rn(O[nt][0] * inv0, O[nt][1] * inv0);
        *reinterpret_cast<__half2*>(aob + 8 * 256 + col) =
            __floats2half2_rn(O[nt][2] * inv1, O[nt][3] * inv1);
    }
}

// ---------------- transpose x: (bc, 256, 1024) -> (bc, 1024, 256) fp16 ----------
__global__ __launch_bounds__(256) void transpose_kernel(
    const float* __restrict__ x, __half* __restrict__ xh)
{
    __shared__ float tile[32][33];
    const int bz = blockIdx.z;
    const float* xs = x + (long long)bz * 256 * 1024;
    __half* xhd = xh + (long long)bz * 1024 * 256;
    const int t0 = blockIdx.x * 32, d0 = blockIdx.y * 32;
    const int tx = threadIdx.x, ty = threadIdx.y;
#pragma unroll
    for (int k = 0; k < 4; k++)
        tile[ty + k * 8][tx] = xs[(long long)(d0 + ty + k * 8) * 1024 + t0 + tx];
    __syncthreads();
#pragma unroll
    for (int k = 0; k < 4; k++)
        xhd[(long long)(t0 + ty + k * 8) * 256 + d0 + tx] =
            __float2half_rn(tile[tx][ty + k * 8]);
}

// ---------------- weight fp32 -> fp16 ----------------
__global__ void cvt_kernel(const float* __restrict__ w, __half* __restrict__ h, int n)
{
    int i = blockIdx.x * 256 + threadIdx.x;
    if (i < n) h[i] = __float2half_rn(w[i]);
}

extern "C" void kernel_launch(void* const* d_in, const int* in_sizes, int n_in,
                              void* d_out, int out_size)
{
    const float* x     = (const float*)d_in[0];   // (8,4,256,1024)
    const int*   mask  = (const int*)d_in[1];     // (8,4,1024,1024) bool -> int32
    const float* w_qkv = (const float*)d_in[2];   // (768,256)
    const float* b_qkv = (const float*)d_in[3];   // (768,)
    const float* w_out = (const float*)d_in[4];   // (256,256)
    const float* b_out = (const float*)d_in[5];   // (256,)
    float*       out   = (float*)d_out;           // (8,4,1024,256)

    __half *xt, *qk, *vt, *ao, *wq, *wo;
    cudaGetSymbolAddress((void**)&xt, g_xt);
    cudaGetSymbolAddress((void**)&qk, g_qk);
    cudaGetSymbolAddress((void**)&vt, g_vt);
    cudaGetSymbolAddress((void**)&ao, g_ao);
    cudaGetSymbolAddress((void**)&wq, g_wq);
    cudaGetSymbolAddress((void**)&wo, g_wo);

    // 0) converters
    transpose_kernel<<<dim3(32, 8, 32), dim3(32, 8)>>>(x, xt);
    cvt_kernel<<<768, 256>>>(w_qkv, wq, 768 * 256);
    cvt_kernel<<<256, 256>>>(w_out, wo, 256 * 256);

    // 1) QKV: Q,K -> qk fp16; V -> vt fp16 (transposed)
    {
        auto kfn = hgemm<256, 256, 256, 512, 1024ll * 256, 0ll, 1024ll * 512,
                         true, false, true, true>;
        cudaFuncSetAttribute(kfn, cudaFuncAttributeMaxDynamicSharedMemorySize, SMEM_BYTES);
        kfn<<<dim3(6, 8, 32), 256, SMEM_BYTES>>>(
            xt, wq, nullptr, qk, vt, b_qkv);
    }

    // 2) fused attention: ao = softmax(mask(QK^T/16)) @ V   (fp16)
    cudaFuncSetAttribute(attn_kernel, cudaFuncAttributeMaxDynamicSharedMemorySize, ATT_SMEM);
    attn_kernel<<<dim3(8, 32), 256, ATT_SMEM>>>(qk, vt, ao, mask);

    // 3) out (fp32) = ao @ w_out^T + b_out
    {
        auto kfn = hgemm<256, 256, 256, 256, 1024ll * 256, 0ll, 1024ll * 256,
                         true, true, false, false>;
        cudaFuncSetAttribute(kfn, cudaFuncAttributeMaxDynamicSharedMemorySize, SMEM_BYTES);
        kfn<<<dim3(2, 8, 32), 256, SMEM_BYTES>>>(
            ao, wo, out, nullptr, nullptr, b_out);
    }
}

// round 15
// speedup vs baseline: 2.2167x; 1.0025x over previous
#include <cuda_runtime.h>
#include <cuda_fp16.h>
#include <cstdint>

// ---------------- scratch (fp16, single plane) ----------------
#define XT_N (32ll * 1024 * 256)
#define QK_N (32ll * 1024 * 512)
#define VT_N (32ll * 256 * 1024)
#define AO_N (32ll * 1024 * 256)
#define WQ_N (768ll * 256)
#define WO_N (256ll * 256)

__device__ __half g_xt[XT_N];
__device__ __half g_qk[QK_N];
__device__ __half g_vt[VT_N];
__device__ __half g_ao[AO_N];
__device__ __half g_wq[WQ_N];
__device__ __half g_wo[WO_N];

__device__ __forceinline__ uint32_t smem_u32(const void* p) {
    uint32_t a;
    asm("{ .reg .u64 t; cvta.to.shared.u64 t, %1; cvt.u32.u64 %0, t; }" : "=r"(a) : "l"(p));
    return a;
}

#define CP_ASYNC16(dst, src) \
    asm volatile("cp.async.cg.shared.global [%0], [%1], 16;" :: "r"(dst), "l"(src))
#define CP_COMMIT() asm volatile("cp.async.commit_group;")
#define CP_WAIT(n)  asm volatile("cp.async.wait_group %0;" :: "n"(n))

#define LDSM4(r0, r1, r2, r3, addr)                                               \
    asm volatile("ldmatrix.sync.aligned.m8n8.x4.shared.b16 {%0,%1,%2,%3}, [%4];"  \
                 : "=r"(r0), "=r"(r1), "=r"(r2), "=r"(r3) : "r"(addr))

#define MMA16816(c, a, b0, b1)                                                    \
    asm volatile("mma.sync.aligned.m16n8k16.row.col.f32.f16.f16.f32 "             \
                 "{%0,%1,%2,%3},{%4,%5,%6,%7},{%8,%9},{%0,%1,%2,%3};"             \
                 : "+f"((c)[0]), "+f"((c)[1]), "+f"((c)[2]), "+f"((c)[3])         \
                 : "r"((a)[0]), "r"((a)[1]), "r"((a)[2]), "r"((a)[3]),            \
                   "r"(b0), "r"(b1))

// Tile chunks: rows x 32 halves = 64 B/row, XOR-swizzled 16B granules.
__device__ __forceinline__ uint32_t sws(int row, int khalf) {
    return (uint32_t)(row * 64 + ((((khalf >> 3) ^ (row >> 1)) & 3) << 4));
}

// ======================= generic hgemm (QKV / out-proj) =======================
#define TILE_B   8192
#define OFF_A    0
#define OFF_B    8192
#define BUF_B    16384
#define NSTAGE   3
#define SMEM_BYTES (NSTAGE * BUF_B)        // 49152 B

template<int K, int LDA, int LDB, int LDC,
         long long SA, long long SB, long long SC,
         bool HAS_BIAS, bool OUT_F32, bool OUT_HALF, bool QKV>
__global__ __launch_bounds__(256, 2) void hgemm(
    const __half* __restrict__ Ah, const __half* __restrict__ Bh,
    float* __restrict__ C32, __half* __restrict__ Ch, __half* __restrict__ VTh,
    const float* __restrict__ bias_n)
{
    extern __shared__ char smem[];
    const uint32_t sbase = smem_u32(smem);
    const int tid = threadIdx.x;
    const int wid = tid >> 5, lane = tid & 31;
    const int bz = blockIdx.z;
    const int n0 = blockIdx.x * 128, m0 = blockIdx.y * 128;
    const int warp_m = wid & 1, warp_n = wid >> 1;

    const __half* Ahb = Ah + bz * SA + (long long)m0 * LDA;
    const __half* Bhb = Bh + bz * SB + (long long)n0 * LDB;

    float acc[4][4][4];
#pragma unroll
    for (int mt = 0; mt < 4; mt++)
#pragma unroll
        for (int nt = 0; nt < 4; nt++)
#pragma unroll
            for (int r = 0; r < 4; r++) acc[mt][nt][r] = 0.f;

    auto CP_TILES = [&](int ch, int buf) {
        const int k0 = ch << 5;
        const uint32_t sb = sbase + buf * BUF_B;
#pragma unroll
        for (int i = 0; i < 2; i++) {
            const int c = tid + i * 256;
            const int row = c >> 2, part = c & 3;
            const uint32_t doff = sws(row, part << 3);
            CP_ASYNC16(sb + OFF_A + doff, Ahb + (long long)row * LDA + k0 + part * 8);
            CP_ASYNC16(sb + OFF_B + doff, Bhb + (long long)row * LDB + k0 + part * 8);
        }
    };

    const int a_row = warp_m * 64 + (lane & 7) + ((lane >> 3) & 1) * 8;
    const int a_kq  = (lane >> 4) * 8;
    const int b_row = warp_n * 32 + (lane >> 4) * 8 + (lane & 7);
    const int b_kq  = ((lane >> 3) & 1) * 8;

    auto COMPUTE = [&](int buf) {
        const uint32_t o = sbase + buf * BUF_B;
#pragma unroll
        for (int s = 0; s < 2; s++) {
            uint32_t bh[8];
#pragma unroll
            for (int p = 0; p < 2; p++) {
                const int row = b_row + p * 16;
                LDSM4(bh[p * 4 + 0], bh[p * 4 + 1], bh[p * 4 + 2], bh[p * 4 + 3],
                      o + OFF_B + sws(row, s * 16 + b_kq));
            }
#pragma unroll
            for (int mt = 0; mt < 4; mt++) {
                uint32_t ah[4];
                LDSM4(ah[0], ah[1], ah[2], ah[3],
                      o + OFF_A + sws(a_row + mt * 16, s * 16 + a_kq));
#pragma unroll
                for (int nt = 0; nt < 4; nt++) {
                    const int i0 = (nt >> 1) * 4 + (nt & 1) * 2;
                    MMA16816(acc[mt][nt], ah, bh[i0], bh[i0 + 1]);
                }
            }
        }
    };

    constexpr int nch = K >> 5;
    CP_TILES(0, 0); CP_COMMIT();
    CP_TILES(1, 1); CP_COMMIT();
    int buf = 0, nxt = 2;
    for (int ch = 0; ch < nch; ch++) {
        if (ch + 1 < nch) { CP_WAIT(1); } else { CP_WAIT(0); }
        __syncthreads();
        if (ch + 2 < nch) {
            CP_TILES(ch + 2, nxt);
            CP_COMMIT();
        }
        COMPUTE(buf);
        buf = (buf + 1 == NSTAGE) ? 0 : buf + 1;
        nxt = (nxt + 1 == NSTAGE) ? 0 : nxt + 1;
    }

    const int gid = lane >> 2, q4 = lane & 3;
    const bool vmode = QKV && (n0 >= 512);

    if (!vmode) {
        float* C32b = OUT_F32 ? (C32 + bz * SC) : nullptr;
        __half* Chb = OUT_HALF ? (Ch + bz * SC) : nullptr;
#pragma unroll
        for (int mt = 0; mt < 4; mt++) {
#pragma unroll
            for (int nt = 0; nt < 4; nt++) {
                const int col = n0 + warp_n * 32 + nt * 8 + q4 * 2;
                float b0 = 0.f, b1 = 0.f;
                if (HAS_BIAS) { b0 = bias_n[col]; b1 = bias_n[col + 1]; }
#pragma unroll
                for (int h = 0; h < 2; h++) {
                    const int row = m0 + warp_m * 64 + mt * 16 + gid + h * 8;
                    float v0 = acc[mt][nt][h * 2 + 0] + b0;
                    float v1 = acc[mt][nt][h * 2 + 1] + b1;
                    if (OUT_F32)
                        *reinterpret_cast<float2*>(C32b + (long long)row * LDC + col) =
                            make_float2(v0, v1);
                    if (OUT_HALF)
                        *reinterpret_cast<__half2*>(Chb + (long long)row * LDC + col) =
                            __floats2half2_rn(v0, v1);
                }
            }
        }
    } else {
        __syncthreads();
        __half* sh = reinterpret_cast<__half*>(smem);          // [128 d][136]
#pragma unroll
        for (int mt = 0; mt < 4; mt++) {
#pragma unroll
            for (int nt = 0; nt < 4; nt++) {
                const int cl0 = warp_n * 32 + nt * 8 + q4 * 2;
                const float b0 = bias_n[n0 + cl0];
                const float b1 = bias_n[n0 + cl0 + 1];
#pragma unroll
                for (int h = 0; h < 2; h++) {
                    const int rl = warp_m * 64 + mt * 16 + gid + h * 8;
                    sh[cl0 * 136 + rl] = __float2half_rn(acc[mt][nt][h * 2 + 0] + b0);
                    sh[(cl0 + 1) * 136 + rl] = __float2half_rn(acc[mt][nt][h * 2 + 1] + b1);
                }
            }
        }
        __syncthreads();
        __half* VThb = VTh + bz * (256ll * 1024);
#pragma unroll
        for (int i = tid; i < 128 * 16; i += 256) {
            const int d = i >> 4, seg = i & 15;
            uint4 uh = *reinterpret_cast<const uint4*>(&sh[d * 136 + seg * 8]);
            const long long o2 = (long long)(n0 - 512 + d) * 1024 + m0 + seg * 8;
            *reinterpret_cast<uint4*>(&VThb[o2]) = uh;
        }
    }
}

// ======================= fused attention: S = QK^T, exp, O = E V, /rowsum ==========
// CTA = 128 queries; 8 warps x 16 q-rows. Q resident in SMEM (64KB);
// K/V streamed in 64-key tiles, double-buffered (2 x 64KB). 1 CTA/SM.
#define ATT_Q_OFF   0
#define ATT_STG_OFF 65536
#define ATT_STG_B   65536
#define ATT_SMEM    (65536 + 2 * 65536)   // 196608

__global__ __launch_bounds__(256, 1) void attn_kernel(
    const __half* __restrict__ qk,   // (bc, 1024, 512): Q cols 0..255, K cols 256..511
    const __half* __restrict__ vt,   // (bc, 256, 1024)
    __half* __restrict__ ao,         // (bc, 1024, 256)
    const int* __restrict__ mask)    // (bc, 1024, 1024)
{
    extern __shared__ char smem[];
    const uint32_t sb = smem_u32(smem);
    const int tid = threadIdx.x, wq = tid >> 5, lane = tid & 31;
    const int qt = blockIdx.x, bz = blockIdx.y;
    const int gid = lane >> 2, q4 = lane & 3;

    const __half* qkb = qk + (long long)bz * 524288;
    const __half* vtb = vt + (long long)bz * 262144;
    const int* mkb = mask + (long long)bz * 1048576;

    // ---- Q load: 8 d-chunks x (128 rows x 32 halves) ----
#pragma unroll
    for (int i = 0; i < 16; i++) {
        const int g = tid + i * 256;
        const int ch = g >> 9, rem = g & 511, row = rem >> 2, part = rem & 3;
        CP_ASYNC16(sb + ATT_Q_OFF + ch * 8192 + sws(row, part * 8),
                   qkb + (long long)(qt * 128 + row) * 512 + ch * 32 + part * 8);
    }

    // K tile: 8 d-chunks x (64 rows x 32 halves) at +0; V tile: 2 t-chunks x (256 x 32) at +32768
    auto LOAD_KV = [&](int kt, int stg) {
        const uint32_t so = sb + ATT_STG_OFF + stg * ATT_STG_B;
#pragma unroll
        for (int i = 0; i < 16; i++) {
            const int g = tid + i * 256;
            if (g < 2048) {
                const int ch = g >> 8, rem = g & 255, row = rem >> 2, part = rem & 3;
                CP_ASYNC16(so + ch * 4096 + sws(row, part * 8),
                           qkb + (long long)(kt * 64 + row) * 512 + 256 + ch * 32 + part * 8);
            } else {
                const int g2 = g - 2048;
                const int tc = g2 >> 10, rem = g2 & 1023, row = rem >> 2, part = rem & 3;
                CP_ASYNC16(so + 32768 + tc * 16384 + sws(row, part * 8),
                           vtb + (long long)row * 1024 + kt * 64 + tc * 32 + part * 8);
            }
        }
    };
    LOAD_KV(0, 0); CP_COMMIT();      // group includes Q
    LOAD_KV(1, 1); CP_COMMIT();

    float O[32][4];
#pragma unroll
    for (int i = 0; i < 32; i++)
#pragma unroll
        for (int j = 0; j < 4; j++) O[i][j] = 0.f;
    float rs0 = 0.f, rs1 = 0.f;

    const int arow = wq * 16 + (lane & 7) + ((lane >> 3) & 1) * 8;
    const int akq  = (lane >> 4) * 8;
    const int brow8 = (lane >> 4) * 8 + (lane & 7);
    const int bkq  = ((lane >> 3) & 1) * 8;
    const long long mrow0 = (long long)(qt * 128 + wq * 16 + gid) * 1024;

    for (int kt = 0; kt < 16; kt++) {
        if (kt + 1 < 16) { CP_WAIT(1); } else { CP_WAIT(0); }
        __syncthreads();
        const uint32_t so = sb + ATT_STG_OFF + (kt & 1) * ATT_STG_B;

#pragma unroll
        for (int ks = 0; ks < 2; ks++) {
            // mask prefetch (independent of MMAs below -> latency hidden)
            int2 mv[8];
            const int kb0 = kt * 64 + ks * 32;
#pragma unroll
            for (int nt = 0; nt < 4; nt++) {
                const int col = kb0 + nt * 8 + q4 * 2;
                mv[nt * 2]     = *reinterpret_cast<const int2*>(mkb + mrow0 + col);
                mv[nt * 2 + 1] = *reinterpret_cast<const int2*>(mkb + mrow0 + 8192 + col);
            }
            // S = Q . K^T  (16 q x 32 k per warp)
            float s[4][4];
#pragma unroll
            for (int nt = 0; nt < 4; nt++)
#pragma unroll
                for (int j = 0; j < 4; j++) s[nt][j] = 0.f;
#pragma unroll
            for (int dch = 0; dch < 8; dch++) {
#pragma unroll
                for (int st = 0; st < 2; st++) {
                    uint32_t aq[4];
                    LDSM4(aq[0], aq[1], aq[2], aq[3],
                          sb + ATT_Q_OFF + dch * 8192 + sws(arow, st * 16 + akq));
                    uint32_t bh[8];
#pragma unroll
                    for (int kb = 0; kb < 2; kb++) {
                        const int krow = ks * 32 + kb * 16 + brow8;
                        LDSM4(bh[kb * 4], bh[kb * 4 + 1], bh[kb * 4 + 2], bh[kb * 4 + 3],
                              so + dch * 4096 + sws(krow, st * 16 + bkq));
                    }
#pragma unroll
                    for (int nt = 0; nt < 4; nt++) {
                        const int i0 = (nt >> 1) * 4 + (nt & 1) * 2;
                        MMA16816(s[nt], aq, bh[i0], bh[i0 + 1]);
                    }
                }
            }
            // mask -> exp -> rowsum -> repack to A-fragments
            uint32_t eA[2][4];
#pragma unroll
            for (int half = 0; half < 2; half++) {
#pragma unroll
                for (int j = 0; j < 2; j++) {
                    const int nt = half * 2 + j;
                    const float e0 = mv[nt * 2].x     ? 0.f : __expf(s[nt][0] * 0.0625f);
                    const float e1 = mv[nt * 2].y     ? 0.f : __expf(s[nt][1] * 0.0625f);
                    const float e2 = mv[nt * 2 + 1].x ? 0.f : __expf(s[nt][2] * 0.0625f);
                    const float e3 = mv[nt * 2 + 1].y ? 0.f : __expf(s[nt][3] * 0.0625f);
                    rs0 += e0 + e1;
                    rs1 += e2 + e3;
                    __half2 h01 = __floats2half2_rn(e0, e1);
                    __half2 h23 = __floats2half2_rn(e2, e3);
                    eA[half][j * 2]     = *reinterpret_cast<uint32_t*>(&h01);
                    eA[half][j * 2 + 1] = *reinterpret_cast<uint32_t*>(&h23);
                }
            }
            // O += E . V   (16 q x 256 d, k = 32 keys)
#pragma unroll
            for (int dblk = 0; dblk < 16; dblk++) {
#pragma unroll
                for (int kstep = 0; kstep < 2; kstep++) {
                    uint32_t bv[4];
                    LDSM4(bv[0], bv[1], bv[2], bv[3],
                          so + 32768 + ks * 16384 + sws(dblk * 16 + brow8, kstep * 16 + bkq));
                    MMA16816(O[dblk * 2],     eA[kstep], bv[0], bv[1]);
                    MMA16816(O[dblk * 2 + 1], eA[kstep], bv[2], bv[3]);
                }
            }
        }
        __syncthreads();
        if (kt + 2 < 16) { LOAD_KV(kt + 2, kt & 1); CP_COMMIT(); }
    }

    // ---- epilogue: rowsum reduce, normalize, store fp16 ----
    rs0 += __shfl_xor_sync(0xffffffffu, rs0, 1);
    rs0 += __shfl_xor_sync(0xffffffffu, rs0, 2);
    rs1 += __shfl_xor_sync(0xffffffffu, rs1, 1);
    rs1 += __shfl_xor_sync(0xffffffffu, rs1, 2);
    const float inv0 = __frcp_rn(rs0), inv1 = __frcp_rn(rs1);

    __half* aob = ao + (long long)bz * 262144 + (long long)(qt * 128 + wq * 16 + gid) * 256;
#pragma unroll
    for (int nt = 0; nt < 32; nt++) {
        const int col = nt * 8 + q4 * 2;
        *reinterpret_cast<__half2*>(aob + col) =
            __floats2half2_rn(O[nt][0] * inv0, O[nt][1] * inv0);
        *reinterpret_cast<__half2*>(aob + 8 * 256 + col) =
            __floats2half2_rn(O[nt][2] * inv1, O[nt][3] * inv1);
    }
}

// ---------------- transpose x: (bc, 256, 1024) -> (bc, 1024, 256) fp16 ----------
__global__ __launch_bounds__(256) void transpose_kernel(
    const float* __restrict__ x, __half* __restrict__ xh)
{
    __shared__ float tile[32][33];
    const int bz = blockIdx.z;
    const float* xs = x + (long long)bz * 256 * 1024;
    __half* xhd = xh + (long long)bz * 1024 * 256;
    const int t0 = blockIdx.x * 32, d0 = blockIdx.y * 32;
    const int tx = threadIdx.x, ty = threadIdx.y;
#pragma unroll
    for (int k = 0; k < 4; k++)
        tile[ty + k * 8][tx] = xs[(long long)(d0 + ty + k * 8) * 1024 + t0 + tx];
    __syncthreads();
#pragma unroll
    for (int k = 0; k < 4; k++)
        xhd[(long long)(t0 + ty + k * 8) * 256 + d0 + tx] =
            __float2half_rn(tile[tx][ty + k * 8]);
}

// ---------------- weight fp32 -> fp16 ----------------
__global__ void cvt_kernel(const float* __restrict__ w, __half* __restrict__ h, int n)
{
    int i = blockIdx.x * 256 + threadIdx.x;
    if (i < n) h[i] = __float2half_rn(w[i]);
}

extern "C" void kernel_launch(void* const* d_in, const int* in_sizes, int n_in,
                              void* d_out, int out_size)
{
    const float* x     = (const float*)d_in[0];   // (8,4,256,1024)
    const int*   mask  = (const int*)d_in[1];     // (8,4,1024,1024) bool -> int32
    const float* w_qkv = (const float*)d_in[2];   // (768,256)
    const float* b_qkv = (const float*)d_in[3];   // (768,)
    const float* w_out = (const float*)d_in[4];   // (256,256)
    const float* b_out = (const float*)d_in[5];   // (256,)
    float*       out   = (float*)d_out;           // (8,4,1024,256)

    __half *xt, *qk, *vt, *ao, *wq, *wo;
    cudaGetSymbolAddress((void**)&xt, g_xt);
    cudaGetSymbolAddress((void**)&qk, g_qk);
    cudaGetSymbolAddress((void**)&vt, g_vt);
    cudaGetSymbolAddress((void**)&ao, g_ao);
    cudaGetSymbolAddress((void**)&wq, g_wq);
    cudaGetSymbolAddress((void**)&wo, g_wo);

    // 0) converters
    transpose_kernel<<<dim3(32, 8, 32), dim3(32, 8)>>>(x, xt);
    cvt_kernel<<<768, 256>>>(w_qkv, wq, 768 * 256);
    cvt_kernel<<<256, 256>>>(w_out, wo, 256 * 256);

    // 1) QKV: Q,K -> qk fp16; V -> vt fp16 (transposed)
    {
        auto kfn = hgemm<256, 256, 256, 512, 1024ll * 256, 0ll, 1024ll * 512,
                         true, false, true, true>;
        cudaFuncSetAttribute(kfn, cudaFuncAttributeMaxDynamicSharedMemorySize, SMEM_BYTES);
        kfn<<<dim3(6, 8, 32), 256, SMEM_BYTES>>>(
            xt, wq, nullptr, qk, vt, b_qkv);
    }

    // 2) fused attention: ao = softmax(mask(QK^T/16)) @ V   (fp16)
    cudaFuncSetAttribute(attn_kernel, cudaFuncAttributeMaxDynamicSharedMemorySize, ATT_SMEM);
    attn_kernel<<<dim3(8, 32), 256, ATT_SMEM>>>(qk, vt, ao, mask);

    // 3) out (fp32) = ao @ w_out^T + b_out
    {
        auto kfn = hgemm<256, 256, 256, 256, 1024ll * 256, 0ll, 1024ll * 256,
                         true, true, false, false>;
        cudaFuncSetAttribute(kfn, cudaFuncAttributeMaxDynamicSharedMemorySize, SMEM_BYTES);
        kfn<<<dim3(2, 8, 32), 256, SMEM_BYTES>>>(
            ao, wo, out, nullptr, nullptr, b_out);
    }
}